// round 4
// baseline (speedup 1.0000x reference)
#include <cuda_runtime.h>
#include <cuda_bf16.h>
#include <math.h>
#include <stdint.h>

// Problem constants
#define BB 8
#define SS 512
#define CC 1024
#define HH 16
#define HD 64
#define RR 32
#define MTOT (BB*SS)          // 4096 rows

// ---------------- scratch (static device arrays; no allocation) -------------
__device__ float g_qkv[MTOT * 3 * CC];   // 48 MB
__device__ float g_xo [MTOT * CC];       // 16 MB
__device__ float g_h  [MTOT * CC];       // 16 MB
__device__ float g_xo2[MTOT * CC];       // 16 MB
__device__ float g_a2 [MTOT * RR];       // 512 KB

// ---------------- small GEMM: A2[M,32] = A[M,K] @ LA[K,32] ------------------
__global__ __launch_bounds__(256) void gemm_la_kernel(
    const float* __restrict__ A, const float* __restrict__ LA,
    float* __restrict__ A2, int K)
{
    __shared__ float sA[128 * 32];       // 128 rows x 32 k
    __shared__ float sLAt[32 * 36];      // [c][k], padded stride 36
    const int tid  = threadIdx.x;
    const int row0 = blockIdx.x * 128;
    const int col  = tid & 31;           // lora rank index
    const int rbase = tid >> 5;          // 0..7

    float s[16];
#pragma unroll
    for (int i = 0; i < 16; i++) s[i] = 0.f;

    for (int k0 = 0; k0 < K; k0 += 32) {
        __syncthreads();
#pragma unroll
        for (int t = 0; t < 4; t++) {
            int i4 = tid + t * 256;          // float4 index 0..1023
            int r  = i4 >> 3;
            int c  = (i4 & 7) * 4;
            *(float4*)&sA[r * 32 + c] =
                *(const float4*)(A + (size_t)(row0 + r) * K + k0 + c);
        }
#pragma unroll
        for (int t = 0; t < 4; t++) {
            int idx = tid + t * 256;         // 0..1023
            int kk  = idx >> 5;
            int c   = idx & 31;
            sLAt[c * 36 + kk] = LA[(size_t)(k0 + kk) * 32 + c];
        }
        __syncthreads();
#pragma unroll
        for (int kk = 0; kk < 32; kk += 4) {
            float4 la = *(const float4*)&sLAt[col * 36 + kk];
#pragma unroll
            for (int rr = 0; rr < 16; rr++) {
                float4 a = *(const float4*)&sA[(rbase + rr * 8) * 32 + kk];
                s[rr] += a.x * la.x + a.y * la.y + a.z * la.z + a.w * la.w;
            }
        }
    }
#pragma unroll
    for (int rr = 0; rr < 16; rr++)
        A2[(size_t)(row0 + rbase + rr * 8) * 32 + col] = s[rr];
}

// ---------------- main SGEMM 128x128x8, 256 threads, 8x8 per thread ---------
// C = A[M,K] @ B[K,N]  (+ bias)  (+ A2[M,32] @ LB[32,N])  (gelu?)  (+ res)
__device__ __forceinline__ float gelu_exact(float x) {
    return 0.5f * x * (1.0f + erff(x * 0.70710678118654752440f));
}

__global__ __launch_bounds__(256) void sgemm128_kernel(
    const float* __restrict__ A, const float* __restrict__ B,
    float* __restrict__ C, int M, int N, int K,
    const float* __restrict__ bias,
    const float* __restrict__ A2, const float* __restrict__ LB,
    const float* __restrict__ res, int act)
{
    __shared__ float As[8][128];
    __shared__ float Bs[8][128];
    __shared__ float sA2t[32 * 129];   // [rank][row], pad 129: conflict-free stores
    __shared__ float sLB[32 * 128];    // [rank][col]

    const int tid = threadIdx.x;
    const int bx = blockIdx.x, by = blockIdx.y;
    const int tx = tid & 15, ty = tid >> 4;

    const int arow = tid >> 1;
    const int acol = (tid & 1) * 4;
    const int brow = tid >> 5;
    const int bcol = (tid & 31) * 4;

    const float* Aptr = A + (size_t)(by * 128 + arow) * K + acol;
    const float* Bptr = B + (size_t)brow * N + bx * 128 + bcol;

    float acc[8][8];
#pragma unroll
    for (int i = 0; i < 8; i++)
#pragma unroll
        for (int j = 0; j < 8; j++) acc[i][j] = 0.f;

    float4 av = *(const float4*)(Aptr);
    float4 bv = *(const float4*)(Bptr);

    for (int k0 = 0; k0 < K; k0 += 8) {
        As[acol + 0][arow] = av.x;
        As[acol + 1][arow] = av.y;
        As[acol + 2][arow] = av.z;
        As[acol + 3][arow] = av.w;
        *(float4*)&Bs[brow][bcol] = bv;
        __syncthreads();
        if (k0 + 8 < K) {
            av = *(const float4*)(Aptr + k0 + 8);
            bv = *(const float4*)(Bptr + (size_t)(k0 + 8) * N);
        }
#pragma unroll
        for (int kk = 0; kk < 8; kk++) {
            float a[8], b[8];
            *(float4*)&a[0] = *(const float4*)&As[kk][ty * 8];
            *(float4*)&a[4] = *(const float4*)&As[kk][ty * 8 + 4];
            *(float4*)&b[0] = *(const float4*)&Bs[kk][tx * 8];
            *(float4*)&b[4] = *(const float4*)&Bs[kk][tx * 8 + 4];
#pragma unroll
            for (int i = 0; i < 8; i++)
#pragma unroll
                for (int j = 0; j < 8; j++)
                    acc[i][j] += a[i] * b[j];
        }
        __syncthreads();
    }

    // LoRA rank-32 update: acc += A2_tile(128x32) @ LB_tile(32x128)
    if (A2) {
#pragma unroll
        for (int t = 0; t < 16; t++) {
            int idx = tid + t * 256;           // 0..4095
            int r = idx >> 5, c = idx & 31;
            sA2t[c * 129 + r] = A2[(size_t)(by * 128 + r) * 32 + c];
        }
#pragma unroll
        for (int t = 0; t < 4; t++) {
            int i4 = tid + t * 256;            // float4 idx 0..1023
            int r = i4 >> 5, c = (i4 & 31) * 4;
            *(float4*)&sLB[r * 128 + c] =
                *(const float4*)(LB + (size_t)r * N + bx * 128 + c);
        }
        __syncthreads();
#pragma unroll
        for (int r = 0; r < 32; r++) {
            float a2v[8], lbv[8];
#pragma unroll
            for (int i = 0; i < 8; i++) a2v[i] = sA2t[r * 129 + ty * 8 + i];
            *(float4*)&lbv[0] = *(const float4*)&sLB[r * 128 + tx * 8];
            *(float4*)&lbv[4] = *(const float4*)&sLB[r * 128 + tx * 8 + 4];
#pragma unroll
            for (int i = 0; i < 8; i++)
#pragma unroll
                for (int j = 0; j < 8; j++)
                    acc[i][j] += a2v[i] * lbv[j];
        }
    }

    // epilogue
#pragma unroll
    for (int i = 0; i < 8; i++) {
        int row = by * 128 + ty * 8 + i;
        size_t base = (size_t)row * N + bx * 128 + tx * 8;
#pragma unroll
        for (int j = 0; j < 8; j++) {
            float v = acc[i][j];
            if (bias) v += bias[bx * 128 + tx * 8 + j];
            if (act == 1) v = gelu_exact(v);
            if (res) v += res[base + j];
            C[base + j] = v;
        }
    }
}

// ---------------- attention: flash-style, 1 thread = 1 query row ------------
// grid (S/128, B*H), 128 threads
// mask is int32 (harness materializes jax bool as int32)
__global__ __launch_bounds__(128) void attn_kernel(
    const float* __restrict__ qkv, const int* __restrict__ mask,
    float* __restrict__ xo)
{
    __shared__ float ks[64][64];
    __shared__ float vs[64][64];
    __shared__ int ms[64];

    const int bh = blockIdx.y;
    const int b = bh >> 4;
    const int h = bh & 15;
    const int qrow = blockIdx.x * 128 + threadIdx.x;   // 0..511
    const float scale = 0.125f;                        // 64^-0.5

    float q[64], o[64];
    {
        const float* qp = qkv + (size_t)(b * SS + qrow) * 3072 + h * 64;
#pragma unroll
        for (int d = 0; d < 64; d += 4) {
            float4 t = *(const float4*)(qp + d);
            q[d + 0] = t.x * scale; q[d + 1] = t.y * scale;
            q[d + 2] = t.z * scale; q[d + 3] = t.w * scale;
        }
#pragma unroll
        for (int d = 0; d < 64; d++) o[d] = 0.f;
    }

    float mrun = -INFINITY;
    float l = 0.f;

    for (int kb = 0; kb < 8; kb++) {
        __syncthreads();
#pragma unroll
        for (int t = 0; t < 8; t++) {
            int i4 = threadIdx.x + t * 128;   // 0..1023
            int r = i4 >> 4;
            int c = (i4 & 15) * 4;
            size_t rowbase = (size_t)(b * SS + kb * 64 + r) * 3072 + h * 64;
            *(float4*)&ks[r][c] = *(const float4*)(qkv + rowbase + 1024 + c);
            *(float4*)&vs[r][c] = *(const float4*)(qkv + rowbase + 2048 + c);
        }
        if (threadIdx.x < 64)
            ms[threadIdx.x] = mask[(size_t)b * (3 * SS) + kb * 64 + threadIdx.x];
        __syncthreads();

        for (int j = 0; j < 64; j++) {
            if (!ms[j]) continue;             // uniform across block
            float s = 0.f;
            const float4* k4 = (const float4*)&ks[j][0];
#pragma unroll
            for (int d4 = 0; d4 < 16; d4++) {
                float4 kv = k4[d4];
                s += q[4 * d4 + 0] * kv.x + q[4 * d4 + 1] * kv.y
                   + q[4 * d4 + 2] * kv.z + q[4 * d4 + 3] * kv.w;
            }
            float newm = fmaxf(mrun, s);
            float corr = __expf(mrun - newm);   // expf(-inf)=0 on first hit
            float p = __expf(s - newm);
            l = l * corr + p;
            const float4* v4 = (const float4*)&vs[j][0];
#pragma unroll
            for (int d4 = 0; d4 < 16; d4++) {
                float4 vv = v4[d4];
                o[4 * d4 + 0] = o[4 * d4 + 0] * corr + p * vv.x;
                o[4 * d4 + 1] = o[4 * d4 + 1] * corr + p * vv.y;
                o[4 * d4 + 2] = o[4 * d4 + 2] * corr + p * vv.z;
                o[4 * d4 + 3] = o[4 * d4 + 3] * corr + p * vv.w;
            }
            mrun = newm;
        }
    }

    const float inv = (l > 0.f) ? (1.0f / l) : 0.0f;   // all-masked row -> 0
    float* op = xo + (size_t)(b * SS + qrow) * CC + h * 64;
#pragma unroll
    for (int d = 0; d < 64; d += 4) {
        float4 t;
        t.x = o[d + 0] * inv; t.y = o[d + 1] * inv;
        t.z = o[d + 2] * inv; t.w = o[d + 3] * inv;
        *(float4*)(op + d) = t;
    }
}

// ---------------- launch -----------------------------------------------------
extern "C" void kernel_launch(void* const* d_in, const int* in_sizes, int n_in,
                              void* d_out, int out_size)
{
    const float* x        = (const float*)d_in[0];
    const int*   mask     = (const int*)d_in[1];
    const float* qkv_w    = (const float*)d_in[2];
    const float* qkv_la   = (const float*)d_in[3];
    const float* qkv_lb   = (const float*)d_in[4];
    const float* proj_w   = (const float*)d_in[5];
    const float* proj_b   = (const float*)d_in[6];
    const float* proj_la  = (const float*)d_in[7];
    const float* proj_lb  = (const float*)d_in[8];
    const float* fc1_w    = (const float*)d_in[9];
    const float* fc1_b    = (const float*)d_in[10];
    const float* fc1_la   = (const float*)d_in[11];
    const float* fc1_lb   = (const float*)d_in[12];
    const float* fc2_w    = (const float*)d_in[13];
    const float* fc2_b    = (const float*)d_in[14];
    const float* fc2_la   = (const float*)d_in[15];
    const float* fc2_lb   = (const float*)d_in[16];
    float* out = (float*)d_out;

    float *qkv, *xo, *h, *xo2, *a2;
    cudaGetSymbolAddress((void**)&qkv, g_qkv);
    cudaGetSymbolAddress((void**)&xo,  g_xo);
    cudaGetSymbolAddress((void**)&h,   g_h);
    cudaGetSymbolAddress((void**)&xo2, g_xo2);
    cudaGetSymbolAddress((void**)&a2,  g_a2);

    const int M = MTOT;

    // qkv = x @ qkv_w + (x @ qkv_la) @ qkv_lb
    gemm_la_kernel<<<M / 128, 256>>>(x, qkv_la, a2, CC);
    sgemm128_kernel<<<dim3(3 * CC / 128, M / 128), 256>>>(
        x, qkv_w, qkv, M, 3 * CC, CC, nullptr, a2, qkv_lb, nullptr, 0);

    // attention -> xo
    attn_kernel<<<dim3(SS / 128, BB * HH), 128>>>(qkv, mask, xo);

    // h = gelu(xo @ fc1_w + fc1_b + lora)
    gemm_la_kernel<<<M / 128, 256>>>(xo, fc1_la, a2, CC);
    sgemm128_kernel<<<dim3(CC / 128, M / 128), 256>>>(
        xo, fc1_w, h, M, CC, CC, fc1_b, a2, fc1_lb, nullptr, 1);

    // xo2 = xo + (h @ fc2_w + fc2_b + lora)
    gemm_la_kernel<<<M / 128, 256>>>(h, fc2_la, a2, CC);
    sgemm128_kernel<<<dim3(CC / 128, M / 128), 256>>>(
        h, fc2_w, xo2, M, CC, CC, fc2_b, a2, fc2_lb, xo, 0);

    // out = xo2 @ proj_w + proj_b + lora
    gemm_la_kernel<<<M / 128, 256>>>(xo2, proj_la, a2, CC);
    sgemm128_kernel<<<dim3(CC / 128, M / 128), 256>>>(
        xo2, proj_w, out, M, CC, CC, proj_b, a2, proj_lb, nullptr, 0);
}

// round 6
// speedup vs baseline: 1.9966x; 1.9966x over previous
#include <cuda_runtime.h>
#include <cuda_bf16.h>
#include <math.h>
#include <stdint.h>

#define BB 8
#define SS 512
#define CC 1024
#define HH 16
#define RR 32
#define MTOT (BB*SS)          // 4096
#define KK CC                 // GEMM K = 1024

// ---------------- fp32 scratch ----------------------------------------------
__device__ float g_qkv[MTOT * 3 * CC];
__device__ float g_xo [MTOT * CC];
__device__ float g_h  [MTOT * CC];
__device__ float g_xo2[MTOT * CC];
__device__ float g_a2 [MTOT * RR];

// ---------------- bf16 hi/lo scratch ----------------------------------------
__device__ __nv_bfloat16 g_ah[MTOT * CC],  g_al[MTOT * CC];
__device__ __nv_bfloat16 g_a2h[MTOT * RR], g_a2l[MTOT * RR];
__device__ __nv_bfloat16 g_wqkv_h[3*CC*CC], g_wqkv_l[3*CC*CC];   // [N,K]
__device__ __nv_bfloat16 g_wfc1_h[CC*CC],  g_wfc1_l[CC*CC];
__device__ __nv_bfloat16 g_wfc2_h[CC*CC],  g_wfc2_l[CC*CC];
__device__ __nv_bfloat16 g_wproj_h[CC*CC], g_wproj_l[CC*CC];
__device__ __nv_bfloat16 g_lbqkv_h[3*CC*RR], g_lbqkv_l[3*CC*RR]; // [N,32]
__device__ __nv_bfloat16 g_lbfc1_h[CC*RR], g_lbfc1_l[CC*RR];
__device__ __nv_bfloat16 g_lbfc2_h[CC*RR], g_lbfc2_l[CC*RR];
__device__ __nv_bfloat16 g_lbproj_h[CC*RR], g_lbproj_l[CC*RR];

// ---------------- helpers ----------------------------------------------------
__device__ __forceinline__ float gelu_exact(float x) {
    return 0.5f * x * (1.0f + erff(x * 0.70710678118654752440f));
}
__device__ __forceinline__ void mma_bf16(float* c, const uint32_t* a,
                                         uint32_t b0, uint32_t b1) {
    asm volatile(
        "mma.sync.aligned.m16n8k16.row.col.f32.bf16.bf16.f32 "
        "{%0,%1,%2,%3}, {%4,%5,%6,%7}, {%8,%9}, {%0,%1,%2,%3};"
        : "+f"(c[0]), "+f"(c[1]), "+f"(c[2]), "+f"(c[3])
        : "r"(a[0]), "r"(a[1]), "r"(a[2]), "r"(a[3]), "r"(b0), "r"(b1));
}
#define CP_ASYNC16(dst_u32, src_ptr) \
    asm volatile("cp.async.cg.shared.global [%0], [%1], 16;" \
                 :: "r"(dst_u32), "l"(src_ptr))
#define CP_COMMIT() asm volatile("cp.async.commit_group;" ::: "memory")

// ---------------- HMMA bf16x3 GEMM -------------------------------------------
// C[M,N] = (Ah+Al)[M,K] @ (Bh+Bl)[N,K]^T + (A2h+A2l)[M,32] @ (LBh+LBl)[N,32]^T
//          (+bias) (gelu?) (+res)
// grid (N/128, M/128), 256 threads.
// smem stage: 4 matrices (Ah,Al,Bh,Bl), each 128 rows x 40 bf16 (pad) = 10240B
#define TCSTRIDE 80            // bytes per smem row (40 bf16)
#define MATB 10240             // bytes per matrix tile
#define STAGEB (4*MATB)        // 40960
#define DSMB (2*STAGEB)        // 81920

__global__ __launch_bounds__(256, 1) void mm_gemm_kernel(
    const __nv_bfloat16* __restrict__ Ah,  const __nv_bfloat16* __restrict__ Al,
    const __nv_bfloat16* __restrict__ A2h, const __nv_bfloat16* __restrict__ A2l,
    const __nv_bfloat16* __restrict__ Bh,  const __nv_bfloat16* __restrict__ Bl,
    const __nv_bfloat16* __restrict__ LBh, const __nv_bfloat16* __restrict__ LBl,
    float* __restrict__ C, const float* __restrict__ bias,
    const float* __restrict__ res, int act, int N)
{
    extern __shared__ char dsm[];
    const int tid = threadIdx.x;
    const int row0 = blockIdx.y * 128;
    const int col0 = blockIdx.x * 128;
    const int w = tid >> 5, lane = tid & 31;
    const int gid = lane >> 2, t4 = lane & 3;
    const int wm = (w & 3) * 32, wn = (w >> 2) * 64;

    const uint32_t smem0 = (uint32_t)__cvta_generic_to_shared(dsm);

    float acc[2][8][4];
#pragma unroll
    for (int i = 0; i < 2; i++)
#pragma unroll
        for (int j = 0; j < 8; j++)
#pragma unroll
            for (int r = 0; r < 4; r++) acc[i][j][r] = 0.f;

    // ---- stage loader: 2048 16B chunks / 256 threads = 8 per thread ----
    auto load_stage = [&](int buf, int kc) {
        const uint32_t sb = smem0 + buf * STAGEB;
        const bool lora = (kc == 32);
        const int koff = lora ? 0 : kc * 32;
        const int strd = lora ? RR : KK;
        const __nv_bfloat16* p0 = lora ? A2h : Ah;
        const __nv_bfloat16* p1 = lora ? A2l : Al;
        const __nv_bfloat16* p2 = lora ? LBh : Bh;
        const __nv_bfloat16* p3 = lora ? LBl : Bl;
#pragma unroll
        for (int t = 0; t < 8; t++) {
            const int idx = tid + t * 256;       // 0..2047
            const int m = idx >> 9;              // matrix 0..3
            const int r = (idx >> 2) & 127;      // row 0..127
            const int q = idx & 3;               // 16B chunk 0..3
            const __nv_bfloat16* base =
                (m == 0) ? p0 : (m == 1) ? p1 : (m == 2) ? p2 : p3;
            const int grow = ((m < 2) ? row0 : col0) + r;
            const __nv_bfloat16* src = base + (size_t)grow * strd + koff + q * 8;
            const uint32_t dst = sb + m * MATB + r * TCSTRIDE + q * 16;
            CP_ASYNC16(dst, src);
        }
        CP_COMMIT();
    };

    // ---- compute one BK=32 chunk from a stage ----
    auto compute = [&](int buf) {
        const char* st = dsm + buf * STAGEB;
#pragma unroll
        for (int ks = 0; ks < 2; ks++) {
            const int kb = ks * 32;              // 16 bf16 = 32 bytes
            uint32_t a[2][2][4];                 // [mtile][hi/lo][reg]
#pragma unroll
            for (int i = 0; i < 2; i++) {
                const int r0 = (wm + i * 16 + gid) * TCSTRIDE;
                const int r1 = (wm + i * 16 + gid + 8) * TCSTRIDE;
                const int c0 = kb + t4 * 4;
                a[i][0][0] = *(const uint32_t*)(st + r0 + c0);
                a[i][0][1] = *(const uint32_t*)(st + r1 + c0);
                a[i][0][2] = *(const uint32_t*)(st + r0 + c0 + 16);
                a[i][0][3] = *(const uint32_t*)(st + r1 + c0 + 16);
                a[i][1][0] = *(const uint32_t*)(st + MATB + r0 + c0);
                a[i][1][1] = *(const uint32_t*)(st + MATB + r1 + c0);
                a[i][1][2] = *(const uint32_t*)(st + MATB + r0 + c0 + 16);
                a[i][1][3] = *(const uint32_t*)(st + MATB + r1 + c0 + 16);
            }
#pragma unroll
            for (int j = 0; j < 8; j++) {
                const int nr = (wn + j * 8 + gid) * TCSTRIDE + kb + t4 * 4;
                const uint32_t bh0 = *(const uint32_t*)(st + 2 * MATB + nr);
                const uint32_t bh1 = *(const uint32_t*)(st + 2 * MATB + nr + 16);
                const uint32_t bl0 = *(const uint32_t*)(st + 3 * MATB + nr);
                const uint32_t bl1 = *(const uint32_t*)(st + 3 * MATB + nr + 16);
#pragma unroll
                for (int i = 0; i < 2; i++) {
                    mma_bf16(acc[i][j], a[i][0], bh0, bh1);
                    mma_bf16(acc[i][j], a[i][0], bl0, bl1);
                    mma_bf16(acc[i][j], a[i][1], bh0, bh1);
                }
            }
        }
    };

    // ---- pipelined main loop: 32 K-chunks + 1 LoRA chunk ----
    load_stage(0, 0);
    for (int kc = 0; kc < 33; kc++) {
        if (kc + 1 < 33) {
            load_stage((kc + 1) & 1, kc + 1);
            asm volatile("cp.async.wait_group 1;" ::: "memory");
        } else {
            asm volatile("cp.async.wait_group 0;" ::: "memory");
        }
        __syncthreads();
        compute(kc & 1);
        __syncthreads();
    }

    // ---- epilogue straight from registers ----
#pragma unroll
    for (int i = 0; i < 2; i++) {
        const int r0 = row0 + wm + i * 16 + gid;
#pragma unroll
        for (int j = 0; j < 8; j++) {
            const int col = col0 + wn + j * 8 + t4 * 2;
            float v0 = acc[i][j][0], v1 = acc[i][j][1];
            float v2 = acc[i][j][2], v3 = acc[i][j][3];
            if (bias) {
                const float b0 = bias[col], b1 = bias[col + 1];
                v0 += b0; v1 += b1; v2 += b0; v3 += b1;
            }
            if (act) {
                v0 = gelu_exact(v0); v1 = gelu_exact(v1);
                v2 = gelu_exact(v2); v3 = gelu_exact(v3);
            }
            if (res) {
                const float* rp0 = res + (size_t)r0 * N + col;
                const float* rp1 = res + (size_t)(r0 + 8) * N + col;
                v0 += rp0[0]; v1 += rp0[1]; v2 += rp1[0]; v3 += rp1[1];
            }
            float2 p0 = make_float2(v0, v1), p1 = make_float2(v2, v3);
            *(float2*)(C + (size_t)r0 * N + col) = p0;
            *(float2*)(C + (size_t)(r0 + 8) * N + col) = p1;
        }
    }
}

// ---------------- prep kernels ----------------------------------------------
__global__ __launch_bounds__(256) void transpose_convert_kernel(
    const float* __restrict__ W, __nv_bfloat16* __restrict__ Th,
    __nv_bfloat16* __restrict__ Tl, int K, int N)
{
    __shared__ float s[32][33];
    const int tx = threadIdx.x & 31, ty = threadIdx.x >> 5;
    const int n0 = blockIdx.x * 32, k0 = blockIdx.y * 32;
#pragma unroll
    for (int i = 0; i < 4; i++)
        s[ty + 8*i][tx] = W[(size_t)(k0 + ty + 8*i) * N + n0 + tx];
    __syncthreads();
#pragma unroll
    for (int i = 0; i < 4; i++) {
        const int n = ty + 8*i;
        const float v = s[tx][n];
        const __nv_bfloat16 h = __float2bfloat16_rn(v);
        const __nv_bfloat16 l = __float2bfloat16_rn(v - __bfloat162float(h));
        const size_t o = (size_t)(n0 + n) * K + k0 + tx;
        Th[o] = h; Tl[o] = l;
    }
}

__global__ __launch_bounds__(256) void convert_hilo_kernel(
    const float* __restrict__ in, __nv_bfloat16* __restrict__ oh,
    __nv_bfloat16* __restrict__ ol, int n4)
{
    const int i = blockIdx.x * 256 + threadIdx.x;
    if (i >= n4) return;
    const float4 v = ((const float4*)in)[i];
    const __nv_bfloat16 hx = __float2bfloat16_rn(v.x);
    const __nv_bfloat16 hy = __float2bfloat16_rn(v.y);
    const __nv_bfloat16 hz = __float2bfloat16_rn(v.z);
    const __nv_bfloat16 hw = __float2bfloat16_rn(v.w);
    const __nv_bfloat16 lx = __float2bfloat16_rn(v.x - __bfloat162float(hx));
    const __nv_bfloat16 ly = __float2bfloat16_rn(v.y - __bfloat162float(hy));
    const __nv_bfloat16 lz = __float2bfloat16_rn(v.z - __bfloat162float(hz));
    const __nv_bfloat16 lw = __float2bfloat16_rn(v.w - __bfloat162float(hw));
    ((__nv_bfloat162*)oh)[2*i]   = __halves2bfloat162(hx, hy);
    ((__nv_bfloat162*)oh)[2*i+1] = __halves2bfloat162(hz, hw);
    ((__nv_bfloat162*)ol)[2*i]   = __halves2bfloat162(lx, ly);
    ((__nv_bfloat162*)ol)[2*i+1] = __halves2bfloat162(lz, lw);
}

// ---------------- LoRA A-projection: A2[M,32] = A[M,K] @ LA[K,32] -----------
__global__ __launch_bounds__(256) void gemm_la_kernel(
    const float* __restrict__ A, const float* __restrict__ LA,
    float* __restrict__ A2, int K)
{
    __shared__ float sA[32 * 32];
    __shared__ float sLAt[32 * 36];
    const int tid = threadIdx.x;
    const int row0 = blockIdx.x * 32;
    const int col = tid & 31;
    const int rgrp = tid >> 5;

    float s[4] = {0.f, 0.f, 0.f, 0.f};

    for (int k0 = 0; k0 < K; k0 += 32) {
        __syncthreads();
        {
            const int r = tid >> 3, c = (tid & 7) * 4;
            *(float4*)&sA[r * 32 + c] =
                *(const float4*)(A + (size_t)(row0 + r) * K + k0 + c);
        }
#pragma unroll
        for (int t = 0; t < 4; t++) {
            const int idx = tid + t * 256;
            const int kk = idx >> 5, c = idx & 31;
            sLAt[c * 36 + kk] = LA[(size_t)(k0 + kk) * 32 + c];
        }
        __syncthreads();
#pragma unroll
        for (int kk = 0; kk < 32; kk += 4) {
            const float4 la = *(const float4*)&sLAt[col * 36 + kk];
#pragma unroll
            for (int rr = 0; rr < 4; rr++) {
                const float4 a = *(const float4*)&sA[(rgrp + rr * 8) * 32 + kk];
                s[rr] += a.x * la.x + a.y * la.y + a.z * la.z + a.w * la.w;
            }
        }
    }
#pragma unroll
    for (int rr = 0; rr < 4; rr++)
        A2[(size_t)(row0 + rgrp + rr * 8) * 32 + col] = s[rr];
}

// ---------------- attention (unchanged; passed) ------------------------------
__global__ __launch_bounds__(128) void attn_kernel(
    const float* __restrict__ qkv, const int* __restrict__ mask,
    float* __restrict__ xo)
{
    __shared__ float ks[64][64];
    __shared__ float vs[64][64];
    __shared__ int ms[64];

    const int bh = blockIdx.y;
    const int b = bh >> 4;
    const int h = bh & 15;
    const int qrow = blockIdx.x * 128 + threadIdx.x;
    const float scale = 0.125f;

    float q[64], o[64];
    {
        const float* qp = qkv + (size_t)(b * SS + qrow) * 3072 + h * 64;
#pragma unroll
        for (int d = 0; d < 64; d += 4) {
            float4 t = *(const float4*)(qp + d);
            q[d+0] = t.x * scale; q[d+1] = t.y * scale;
            q[d+2] = t.z * scale; q[d+3] = t.w * scale;
        }
#pragma unroll
        for (int d = 0; d < 64; d++) o[d] = 0.f;
    }

    float mrun = -INFINITY;
    float l = 0.f;

    for (int kb = 0; kb < 8; kb++) {
        __syncthreads();
#pragma unroll
        for (int t = 0; t < 8; t++) {
            int i4 = threadIdx.x + t * 128;
            int r = i4 >> 4;
            int c = (i4 & 15) * 4;
            size_t rowbase = (size_t)(b * SS + kb * 64 + r) * 3072 + h * 64;
            *(float4*)&ks[r][c] = *(const float4*)(qkv + rowbase + 1024 + c);
            *(float4*)&vs[r][c] = *(const float4*)(qkv + rowbase + 2048 + c);
        }
        if (threadIdx.x < 64)
            ms[threadIdx.x] = mask[(size_t)b * (3 * SS) + kb * 64 + threadIdx.x];
        __syncthreads();

        for (int j = 0; j < 64; j++) {
            if (!ms[j]) continue;
            float s = 0.f;
            const float4* k4 = (const float4*)&ks[j][0];
#pragma unroll
            for (int d4 = 0; d4 < 16; d4++) {
                float4 kv = k4[d4];
                s += q[4*d4+0]*kv.x + q[4*d4+1]*kv.y + q[4*d4+2]*kv.z + q[4*d4+3]*kv.w;
            }
            float newm = fmaxf(mrun, s);
            float corr = __expf(mrun - newm);
            float p = __expf(s - newm);
            l = l * corr + p;
            const float4* v4 = (const float4*)&vs[j][0];
#pragma unroll
            for (int d4 = 0; d4 < 16; d4++) {
                float4 vv = v4[d4];
                o[4*d4+0] = o[4*d4+0]*corr + p*vv.x;
                o[4*d4+1] = o[4*d4+1]*corr + p*vv.y;
                o[4*d4+2] = o[4*d4+2]*corr + p*vv.z;
                o[4*d4+3] = o[4*d4+3]*corr + p*vv.w;
            }
            mrun = newm;
        }
    }

    const float inv = (l > 0.f) ? (1.0f / l) : 0.0f;
    float* op = xo + (size_t)(b * SS + qrow) * CC + h * 64;
#pragma unroll
    for (int d = 0; d < 64; d += 4) {
        float4 t;
        t.x = o[d+0]*inv; t.y = o[d+1]*inv; t.z = o[d+2]*inv; t.w = o[d+3]*inv;
        *(float4*)(op + d) = t;
    }
}

// ---------------- launch -----------------------------------------------------
extern "C" void kernel_launch(void* const* d_in, const int* in_sizes, int n_in,
                              void* d_out, int out_size)
{
    const float* x        = (const float*)d_in[0];
    const int*   mask     = (const int*)d_in[1];
    const float* qkv_w    = (const float*)d_in[2];
    const float* qkv_la   = (const float*)d_in[3];
    const float* qkv_lb   = (const float*)d_in[4];
    const float* proj_w   = (const float*)d_in[5];
    const float* proj_b   = (const float*)d_in[6];
    const float* proj_la  = (const float*)d_in[7];
    const float* proj_lb  = (const float*)d_in[8];
    const float* fc1_w    = (const float*)d_in[9];
    const float* fc1_b    = (const float*)d_in[10];
    const float* fc1_la   = (const float*)d_in[11];
    const float* fc1_lb   = (const float*)d_in[12];
    const float* fc2_w    = (const float*)d_in[13];
    const float* fc2_b    = (const float*)d_in[14];
    const float* fc2_la   = (const float*)d_in[15];
    const float* fc2_lb   = (const float*)d_in[16];
    float* out = (float*)d_out;

    float *qkv, *xo, *h, *xo2, *a2;
    cudaGetSymbolAddress((void**)&qkv, g_qkv);
    cudaGetSymbolAddress((void**)&xo,  g_xo);
    cudaGetSymbolAddress((void**)&h,   g_h);
    cudaGetSymbolAddress((void**)&xo2, g_xo2);
    cudaGetSymbolAddress((void**)&a2,  g_a2);

    __nv_bfloat16 *ah,*al,*a2h,*a2l,*wqh,*wql,*w1h,*w1l,*w2h,*w2l,*wph,*wpl;
    __nv_bfloat16 *lqh,*lql,*l1h,*l1l,*l2h,*l2l,*lph,*lpl;
    cudaGetSymbolAddress((void**)&ah,  g_ah);   cudaGetSymbolAddress((void**)&al,  g_al);
    cudaGetSymbolAddress((void**)&a2h, g_a2h);  cudaGetSymbolAddress((void**)&a2l, g_a2l);
    cudaGetSymbolAddress((void**)&wqh, g_wqkv_h); cudaGetSymbolAddress((void**)&wql, g_wqkv_l);
    cudaGetSymbolAddress((void**)&w1h, g_wfc1_h); cudaGetSymbolAddress((void**)&w1l, g_wfc1_l);
    cudaGetSymbolAddress((void**)&w2h, g_wfc2_h); cudaGetSymbolAddress((void**)&w2l, g_wfc2_l);
    cudaGetSymbolAddress((void**)&wph, g_wproj_h); cudaGetSymbolAddress((void**)&wpl, g_wproj_l);
    cudaGetSymbolAddress((void**)&lqh, g_lbqkv_h); cudaGetSymbolAddress((void**)&lql, g_lbqkv_l);
    cudaGetSymbolAddress((void**)&l1h, g_lbfc1_h); cudaGetSymbolAddress((void**)&l1l, g_lbfc1_l);
    cudaGetSymbolAddress((void**)&l2h, g_lbfc2_h); cudaGetSymbolAddress((void**)&l2l, g_lbfc2_l);
    cudaGetSymbolAddress((void**)&lph, g_lbproj_h); cudaGetSymbolAddress((void**)&lpl, g_lbproj_l);

    cudaFuncSetAttribute(mm_gemm_kernel,
                         cudaFuncAttributeMaxDynamicSharedMemorySize, DSMB);

    const int M = MTOT;
    const int actN4 = M * CC / 4;
    const int a2N4  = M * RR / 4;

    // ---- weight prep (transpose + hi/lo convert) ----
    transpose_convert_kernel<<<dim3(3*CC/32, CC/32), 256>>>(qkv_w, wqh, wql, CC, 3*CC);
    transpose_convert_kernel<<<dim3(CC/32,  CC/32), 256>>>(fc1_w, w1h, w1l, CC, CC);
    transpose_convert_kernel<<<dim3(CC/32,  CC/32), 256>>>(fc2_w, w2h, w2l, CC, CC);
    transpose_convert_kernel<<<dim3(CC/32,  CC/32), 256>>>(proj_w, wph, wpl, CC, CC);
    transpose_convert_kernel<<<dim3(3*CC/32, 1), 256>>>(qkv_lb, lqh, lql, RR, 3*CC);
    transpose_convert_kernel<<<dim3(CC/32, 1), 256>>>(fc1_lb, l1h, l1l, RR, CC);
    transpose_convert_kernel<<<dim3(CC/32, 1), 256>>>(fc2_lb, l2h, l2l, RR, CC);
    transpose_convert_kernel<<<dim3(CC/32, 1), 256>>>(proj_lb, lph, lpl, RR, CC);

    // ---- qkv ----
    gemm_la_kernel<<<M/32, 256>>>(x, qkv_la, a2, CC);
    convert_hilo_kernel<<<actN4/256, 256>>>(x, ah, al, actN4);
    convert_hilo_kernel<<<a2N4/256, 256>>>(a2, a2h, a2l, a2N4);
    mm_gemm_kernel<<<dim3(3*CC/128, M/128), 256, DSMB>>>(
        ah, al, a2h, a2l, wqh, wql, lqh, lql, qkv, nullptr, nullptr, 0, 3*CC);

    // ---- attention ----
    attn_kernel<<<dim3(SS/128, BB*HH), 128>>>(qkv, mask, xo);

    // ---- fc1 (gelu) ----
    gemm_la_kernel<<<M/32, 256>>>(xo, fc1_la, a2, CC);
    convert_hilo_kernel<<<actN4/256, 256>>>(xo, ah, al, actN4);
    convert_hilo_kernel<<<a2N4/256, 256>>>(a2, a2h, a2l, a2N4);
    mm_gemm_kernel<<<dim3(CC/128, M/128), 256, DSMB>>>(
        ah, al, a2h, a2l, w1h, w1l, l1h, l1l, h, fc1_b, nullptr, 1, CC);

    // ---- fc2 (+ residual xo) ----
    gemm_la_kernel<<<M/32, 256>>>(h, fc2_la, a2, CC);
    convert_hilo_kernel<<<actN4/256, 256>>>(h, ah, al, actN4);
    convert_hilo_kernel<<<a2N4/256, 256>>>(a2, a2h, a2l, a2N4);
    mm_gemm_kernel<<<dim3(CC/128, M/128), 256, DSMB>>>(
        ah, al, a2h, a2l, w2h, w2l, l2h, l2l, xo2, fc2_b, xo, 0, CC);

    // ---- proj ----
    gemm_la_kernel<<<M/32, 256>>>(xo2, proj_la, a2, CC);
    convert_hilo_kernel<<<actN4/256, 256>>>(xo2, ah, al, actN4);
    convert_hilo_kernel<<<a2N4/256, 256>>>(a2, a2h, a2l, a2N4);
    mm_gemm_kernel<<<dim3(CC/128, M/128), 256, DSMB>>>(
        ah, al, a2h, a2l, wph, wpl, lph, lpl, out, proj_b, nullptr, 0, CC);
}

// round 9
// speedup vs baseline: 2.1837x; 1.0937x over previous
#include <cuda_runtime.h>
#include <cuda_bf16.h>
#include <math.h>
#include <stdint.h>

#define BB 8
#define SS 512
#define CC 1024
#define HH 16
#define RR 32
#define MTOT (BB*SS)          // 4096
#define KK CC                 // GEMM K = 1024

// ---------------- fp32 scratch ----------------------------------------------
__device__ float g_qkv[MTOT * 3 * CC];
__device__ float g_xo [MTOT * CC];
__device__ float g_h  [MTOT * CC];
__device__ float g_xo2[MTOT * CC];
__device__ float g_a2 [MTOT * RR];

// ---------------- bf16 hi/lo scratch ----------------------------------------
__device__ __nv_bfloat16 g_ah [MTOT * CC], g_al [MTOT * CC];   // buffer pair A
__device__ __nv_bfloat16 g_ah2[MTOT * CC], g_al2[MTOT * CC];   // buffer pair B
__device__ __nv_bfloat16 g_a2h[MTOT * RR], g_a2l[MTOT * RR];
__device__ __nv_bfloat16 g_wqkv_h[3*CC*CC], g_wqkv_l[3*CC*CC]; // [N,K]
__device__ __nv_bfloat16 g_wfc1_h[CC*CC],  g_wfc1_l[CC*CC];
__device__ __nv_bfloat16 g_wfc2_h[CC*CC],  g_wfc2_l[CC*CC];
__device__ __nv_bfloat16 g_wproj_h[CC*CC], g_wproj_l[CC*CC];
__device__ __nv_bfloat16 g_lbqkv_h[3*CC*RR], g_lbqkv_l[3*CC*RR];
__device__ __nv_bfloat16 g_lbfc1_h[CC*RR], g_lbfc1_l[CC*RR];
__device__ __nv_bfloat16 g_lbfc2_h[CC*RR], g_lbfc2_l[CC*RR];
__device__ __nv_bfloat16 g_lbproj_h[CC*RR], g_lbproj_l[CC*RR];

// ---------------- helpers ----------------------------------------------------
__device__ __forceinline__ float gelu_exact(float x) {
    return 0.5f * x * (1.0f + erff(x * 0.70710678118654752440f));
}
__device__ __forceinline__ void mma_bf16(float* c, const uint32_t* a,
                                         uint32_t b0, uint32_t b1) {
    asm volatile(
        "mma.sync.aligned.m16n8k16.row.col.f32.bf16.bf16.f32 "
        "{%0,%1,%2,%3}, {%4,%5,%6,%7}, {%8,%9}, {%0,%1,%2,%3};"
        : "+f"(c[0]), "+f"(c[1]), "+f"(c[2]), "+f"(c[3])
        : "r"(a[0]), "r"(a[1]), "r"(a[2]), "r"(a[3]), "r"(b0), "r"(b1));
}
__device__ __forceinline__ void ldsm4(uint32_t* r, uint32_t addr) {
    asm volatile("ldmatrix.sync.aligned.m8n8.x4.shared.b16 {%0,%1,%2,%3}, [%4];"
        : "=r"(r[0]), "=r"(r[1]), "=r"(r[2]), "=r"(r[3]) : "r"(addr));
}
#define CP_ASYNC16(dst_u32, src_ptr) \
    asm volatile("cp.async.cg.shared.global [%0], [%1], 16;" \
                 :: "r"(dst_u32), "l"(src_ptr))
#define CP_COMMIT() asm volatile("cp.async.commit_group;" ::: "memory")

// ---------------- HMMA bf16x3 GEMM -------------------------------------------
// C[M,N] = (Ah+Al)[M,K] @ (Bh+Bl)[N,K]^T + (A2h+A2l)[M,32] @ (LBh+LBl)[N,32]^T
//          (+bias) (gelu?) (+res), optional bf16 hi/lo output (Ch/Cl)
#define TCSTRIDE 80            // bytes per smem row (40 bf16)
#define MATB 10240             // bytes per matrix tile (128 rows)
#define STAGEB (4*MATB)        // 40960
#define DSMB (2*STAGEB)        // 81920

__global__ __launch_bounds__(256, 2) void mm_gemm_kernel(
    const __nv_bfloat16* __restrict__ Ah,  const __nv_bfloat16* __restrict__ Al,
    const __nv_bfloat16* __restrict__ A2h, const __nv_bfloat16* __restrict__ A2l,
    const __nv_bfloat16* __restrict__ Bh,  const __nv_bfloat16* __restrict__ Bl,
    const __nv_bfloat16* __restrict__ LBh, const __nv_bfloat16* __restrict__ LBl,
    float* __restrict__ C, __nv_bfloat16* __restrict__ Ch,
    __nv_bfloat16* __restrict__ Cl, const float* __restrict__ bias,
    const float* __restrict__ res, int act, int N)
{
    extern __shared__ char dsm[];
    const int tid = threadIdx.x;
    const int row0 = blockIdx.y * 128;
    const int col0 = blockIdx.x * 128;
    const int w = tid >> 5, lane = tid & 31;
    const int gid = lane >> 2, t4 = lane & 3;
    const int wm = (w & 3) * 32, wn = (w >> 2) * 64;

    const uint32_t smem0 = (uint32_t)__cvta_generic_to_shared(dsm);

    // ldmatrix source row/koff (within-tile), reused every chunk
    const int a_r  = (lane & 15);
    const int a_ko = (lane >> 4) * 16;
    const int b_r  = (lane & 7) + ((lane >> 4) << 3);
    const int b_ko = ((lane >> 3) & 1) * 16;

    float acc[2][8][4];
#pragma unroll
    for (int i = 0; i < 2; i++)
#pragma unroll
        for (int j = 0; j < 8; j++)
#pragma unroll
            for (int r = 0; r < 4; r++) acc[i][j][r] = 0.f;

    auto load_stage = [&](int buf, int kc) {
        const uint32_t sb = smem0 + buf * STAGEB;
        const bool lora = (kc == 32);
        const int koff = lora ? 0 : kc * 32;
        const int strd = lora ? RR : KK;
        const __nv_bfloat16* p0 = lora ? A2h : Ah;
        const __nv_bfloat16* p1 = lora ? A2l : Al;
        const __nv_bfloat16* p2 = lora ? LBh : Bh;
        const __nv_bfloat16* p3 = lora ? LBl : Bl;
#pragma unroll
        for (int t = 0; t < 8; t++) {
            const int idx = tid + t * 256;       // 0..2047
            const int m = idx >> 9;              // matrix 0..3
            const int r = (idx >> 2) & 127;      // row 0..127
            const int q = idx & 3;               // 16B chunk 0..3
            const __nv_bfloat16* base =
                (m == 0) ? p0 : (m == 1) ? p1 : (m == 2) ? p2 : p3;
            const int grow = ((m < 2) ? row0 : col0) + r;
            const __nv_bfloat16* src = base + (size_t)grow * strd + koff + q * 8;
            const uint32_t dst = sb + m * MATB + r * TCSTRIDE + q * 16;
            CP_ASYNC16(dst, src);
        }
        CP_COMMIT();
    };

    auto compute = [&](int buf) {
        const uint32_t sb = smem0 + buf * STAGEB;
#pragma unroll
        for (int ks = 0; ks < 2; ks++) {
            const int kb = ks * 32;              // bytes
            uint32_t a[2][2][4];                 // [mtile][hi/lo][reg]
#pragma unroll
            for (int i = 0; i < 2; i++) {
                const uint32_t ra = (wm + i * 16 + a_r) * TCSTRIDE + kb + a_ko;
                ldsm4(a[i][0], sb + ra);
                ldsm4(a[i][1], sb + MATB + ra);
            }
#pragma unroll
            for (int jp = 0; jp < 4; jp++) {
                uint32_t bh[4], bl[4];
                const uint32_t rb = (wn + jp * 16 + b_r) * TCSTRIDE + kb + b_ko;
                ldsm4(bh, sb + 2 * MATB + rb);
                ldsm4(bl, sb + 3 * MATB + rb);
#pragma unroll
                for (int i = 0; i < 2; i++) {
                    mma_bf16(acc[i][2*jp],   a[i][0], bh[0], bh[1]);
                    mma_bf16(acc[i][2*jp],   a[i][0], bl[0], bl[1]);
                    mma_bf16(acc[i][2*jp],   a[i][1], bh[0], bh[1]);
                    mma_bf16(acc[i][2*jp+1], a[i][0], bh[2], bh[3]);
                    mma_bf16(acc[i][2*jp+1], a[i][0], bl[2], bl[3]);
                    mma_bf16(acc[i][2*jp+1], a[i][1], bh[2], bh[3]);
                }
            }
        }
    };

    load_stage(0, 0);
    for (int kc = 0; kc < 33; kc++) {
        if (kc + 1 < 33) {
            load_stage((kc + 1) & 1, kc + 1);
            asm volatile("cp.async.wait_group 1;" ::: "memory");
        } else {
            asm volatile("cp.async.wait_group 0;" ::: "memory");
        }
        __syncthreads();
        compute(kc & 1);
        __syncthreads();
    }

    // ---- epilogue from registers ----
#pragma unroll
    for (int i = 0; i < 2; i++) {
        const int r0 = row0 + wm + i * 16 + gid;
#pragma unroll
        for (int j = 0; j < 8; j++) {
            const int col = col0 + wn + j * 8 + t4 * 2;
            float v0 = acc[i][j][0], v1 = acc[i][j][1];
            float v2 = acc[i][j][2], v3 = acc[i][j][3];
            if (bias) {
                const float b0 = bias[col], b1 = bias[col + 1];
                v0 += b0; v1 += b1; v2 += b0; v3 += b1;
            }
            if (act) {
                v0 = gelu_exact(v0); v1 = gelu_exact(v1);
                v2 = gelu_exact(v2); v3 = gelu_exact(v3);
            }
            if (res) {
                const float* rp0 = res + (size_t)r0 * N + col;
                const float* rp1 = res + (size_t)(r0 + 8) * N + col;
                v0 += rp0[0]; v1 += rp0[1]; v2 += rp1[0]; v3 += rp1[1];
            }
            *(float2*)(C + (size_t)r0 * N + col) = make_float2(v0, v1);
            *(float2*)(C + (size_t)(r0 + 8) * N + col) = make_float2(v2, v3);
            if (Ch) {
                const __nv_bfloat16 h0 = __float2bfloat16_rn(v0);
                const __nv_bfloat16 h1 = __float2bfloat16_rn(v1);
                const __nv_bfloat16 h2 = __float2bfloat16_rn(v2);
                const __nv_bfloat16 h3 = __float2bfloat16_rn(v3);
                *(__nv_bfloat162*)(Ch + (size_t)r0 * N + col) =
                    __halves2bfloat162(h0, h1);
                *(__nv_bfloat162*)(Ch + (size_t)(r0 + 8) * N + col) =
                    __halves2bfloat162(h2, h3);
                *(__nv_bfloat162*)(Cl + (size_t)r0 * N + col) =
                    __halves2bfloat162(__float2bfloat16_rn(v0 - __bfloat162float(h0)),
                                       __float2bfloat16_rn(v1 - __bfloat162float(h1)));
                *(__nv_bfloat162*)(Cl + (size_t)(r0 + 8) * N + col) =
                    __halves2bfloat162(__float2bfloat16_rn(v2 - __bfloat162float(h2)),
                                       __float2bfloat16_rn(v3 - __bfloat162float(h3)));
            }
        }
    }
}

// ---------------- prep kernels ----------------------------------------------
__global__ __launch_bounds__(256) void transpose_convert_kernel(
    const float* __restrict__ W, __nv_bfloat16* __restrict__ Th,
    __nv_bfloat16* __restrict__ Tl, int K, int N)
{
    __shared__ float s[32][33];
    const int tx = threadIdx.x & 31, ty = threadIdx.x >> 5;
    const int n0 = blockIdx.x * 32, k0 = blockIdx.y * 32;
#pragma unroll
    for (int i = 0; i < 4; i++)
        s[ty + 8*i][tx] = W[(size_t)(k0 + ty + 8*i) * N + n0 + tx];
    __syncthreads();
#pragma unroll
    for (int i = 0; i < 4; i++) {
        const int n = ty + 8*i;
        const float v = s[tx][n];
        const __nv_bfloat16 h = __float2bfloat16_rn(v);
        const __nv_bfloat16 l = __float2bfloat16_rn(v - __bfloat162float(h));
        const size_t o = (size_t)(n0 + n) * K + k0 + tx;
        Th[o] = h; Tl[o] = l;
    }
}

__global__ __launch_bounds__(256) void convert_hilo_kernel(
    const float* __restrict__ in, __nv_bfloat16* __restrict__ oh,
    __nv_bfloat16* __restrict__ ol, int n4)
{
    const int i = blockIdx.x * 256 + threadIdx.x;
    if (i >= n4) return;
    const float4 v = ((const float4*)in)[i];
    const __nv_bfloat16 hx = __float2bfloat16_rn(v.x);
    const __nv_bfloat16 hy = __float2bfloat16_rn(v.y);
    const __nv_bfloat16 hz = __float2bfloat16_rn(v.z);
    const __nv_bfloat16 hw = __float2bfloat16_rn(v.w);
    ((__nv_bfloat162*)oh)[2*i]   = __halves2bfloat162(hx, hy);
    ((__nv_bfloat162*)oh)[2*i+1] = __halves2bfloat162(hz, hw);
    ((__nv_bfloat162*)ol)[2*i]   = __halves2bfloat162(
        __float2bfloat16_rn(v.x - __bfloat162float(hx)),
        __float2bfloat16_rn(v.y - __bfloat162float(hy)));
    ((__nv_bfloat162*)ol)[2*i+1] = __halves2bfloat162(
        __float2bfloat16_rn(v.z - __bfloat162float(hz)),
        __float2bfloat16_rn(v.w - __bfloat162float(hw)));
}

// ---------------- LoRA A-projection: A2[M,32] = A[M,K] @ LA[K,32] -----------
__global__ __launch_bounds__(256) void gemm_la_kernel(
    const float* __restrict__ A, const float* __restrict__ LA,
    float* __restrict__ A2, int K)
{
    __shared__ float sA[32 * 32];
    __shared__ float sLAt[32 * 36];
    const int tid = threadIdx.x;
    const int row0 = blockIdx.x * 32;
    const int col = tid & 31;
    const int rgrp = tid >> 5;

    float s[4] = {0.f, 0.f, 0.f, 0.f};

    for (int k0 = 0; k0 < K; k0 += 32) {
        __syncthreads();
        {
            const int r = tid >> 3, c = (tid & 7) * 4;
            *(float4*)&sA[r * 32 + c] =
                *(const float4*)(A + (size_t)(row0 + r) * K + k0 + c);
        }
#pragma unroll
        for (int t = 0; t < 4; t++) {
            const int idx = tid + t * 256;
            const int kk = idx >> 5, c = idx & 31;
            sLAt[c * 36 + kk] = LA[(size_t)(k0 + kk) * 32 + c];
        }
        __syncthreads();
#pragma unroll
        for (int kk = 0; kk < 32; kk += 4) {
            const float4 la = *(const float4*)&sLAt[col * 36 + kk];
#pragma unroll
            for (int rr = 0; rr < 4; rr++) {
                const float4 a = *(const float4*)&sA[(rgrp + rr * 8) * 32 + kk];
                s[rr] += a.x * la.x + a.y * la.y + a.z * la.z + a.w * la.w;
            }
        }
    }
#pragma unroll
    for (int rr = 0; rr < 4; rr++)
        A2[(size_t)(row0 + rgrp + rr * 8) * 32 + col] = s[rr];
}

// ---------------- attention: flash-style + lazy rescale ----------------------
__global__ __launch_bounds__(128) void attn_kernel(
    const float* __restrict__ qkv, const int* __restrict__ mask,
    float* __restrict__ xo, __nv_bfloat16* __restrict__ xoh,
    __nv_bfloat16* __restrict__ xol)
{
    __shared__ float ks[64][64];
    __shared__ float vs[64][64];
    __shared__ int ms[64];

    const int bh = blockIdx.y;
    const int b = bh >> 4;
    const int h = bh & 15;
    const int qrow = blockIdx.x * 128 + threadIdx.x;
    const float scale = 0.125f;

    float q[64], o[64];
    {
        const float* qp = qkv + (size_t)(b * SS + qrow) * 3072 + h * 64;
#pragma unroll
        for (int d = 0; d < 64; d += 4) {
            float4 t = *(const float4*)(qp + d);
            q[d+0] = t.x * scale; q[d+1] = t.y * scale;
            q[d+2] = t.z * scale; q[d+3] = t.w * scale;
        }
#pragma unroll
        for (int d = 0; d < 64; d++) o[d] = 0.f;
    }

    float mrun = -INFINITY;
    float l = 0.f;

    for (int kb = 0; kb < 8; kb++) {
        __syncthreads();
#pragma unroll
        for (int t = 0; t < 8; t++) {
            int i4 = threadIdx.x + t * 128;
            int r = i4 >> 4;
            int c = (i4 & 15) * 4;
            size_t rowbase = (size_t)(b * SS + kb * 64 + r) * 3072 + h * 64;
            *(float4*)&ks[r][c] = *(const float4*)(qkv + rowbase + 1024 + c);
            *(float4*)&vs[r][c] = *(const float4*)(qkv + rowbase + 2048 + c);
        }
        if (threadIdx.x < 64)
            ms[threadIdx.x] = mask[(size_t)b * (3 * SS) + kb * 64 + threadIdx.x];
        __syncthreads();

        for (int j = 0; j < 64; j++) {
            if (!ms[j]) continue;
            float s = 0.f;
            const float4* k4 = (const float4*)&ks[j][0];
#pragma unroll
            for (int d4 = 0; d4 < 16; d4++) {
                float4 kv = k4[d4];
                s += q[4*d4+0]*kv.x + q[4*d4+1]*kv.y + q[4*d4+2]*kv.z + q[4*d4+3]*kv.w;
            }
            const float4* v4 = (const float4*)&vs[j][0];
            if (s > mrun) {
                // rescale path (p = 1)
                const float corr = __expf(mrun - s);   // 0 on first hit
                l = l * corr + 1.f;
#pragma unroll
                for (int d4 = 0; d4 < 16; d4++) {
                    float4 vv = v4[d4];
                    o[4*d4+0] = o[4*d4+0]*corr + vv.x;
                    o[4*d4+1] = o[4*d4+1]*corr + vv.y;
                    o[4*d4+2] = o[4*d4+2]*corr + vv.z;
                    o[4*d4+3] = o[4*d4+3]*corr + vv.w;
                }
                mrun = s;
            } else {
                const float p = __expf(s - mrun);
                l += p;
#pragma unroll
                for (int d4 = 0; d4 < 16; d4++) {
                    float4 vv = v4[d4];
                    o[4*d4+0] += p*vv.x;
                    o[4*d4+1] += p*vv.y;
                    o[4*d4+2] += p*vv.z;
                    o[4*d4+3] += p*vv.w;
                }
            }
        }
    }

    const float inv = (l > 0.f) ? (1.0f / l) : 0.0f;
    const size_t obase = (size_t)(b * SS + qrow) * CC + h * 64;
    float* op = xo + obase;
#pragma unroll
    for (int d = 0; d < 64; d += 4) {
        float4 t;
        t.x = o[d+0]*inv; t.y = o[d+1]*inv; t.z = o[d+2]*inv; t.w = o[d+3]*inv;
        *(float4*)(op + d) = t;
        const __nv_bfloat16 h0 = __float2bfloat16_rn(t.x);
        const __nv_bfloat16 h1 = __float2bfloat16_rn(t.y);
        const __nv_bfloat16 h2 = __float2bfloat16_rn(t.z);
        const __nv_bfloat16 h3 = __float2bfloat16_rn(t.w);
        *(__nv_bfloat162*)(xoh + obase + d)     = __halves2bfloat162(h0, h1);
        *(__nv_bfloat162*)(xoh + obase + d + 2) = __halves2bfloat162(h2, h3);
        *(__nv_bfloat162*)(xol + obase + d) = __halves2bfloat162(
            __float2bfloat16_rn(t.x - __bfloat162float(h0)),
            __float2bfloat16_rn(t.y - __bfloat162float(h1)));
        *(__nv_bfloat162*)(xol + obase + d + 2) = __halves2bfloat162(
            __float2bfloat16_rn(t.z - __bfloat162float(h2)),
            __float2bfloat16_rn(t.w - __bfloat162float(h3)));
    }
}

// ---------------- launch -----------------------------------------------------
extern "C" void kernel_launch(void* const* d_in, const int* in_sizes, int n_in,
                              void* d_out, int out_size)
{
    const float* x        = (const float*)d_in[0];
    const int*   mask     = (const int*)d_in[1];
    const float* qkv_w    = (const float*)d_in[2];
    const float* qkv_la   = (const float*)d_in[3];
    const float* qkv_lb   = (const float*)d_in[4];
    const float* proj_w   = (const float*)d_in[5];
    const float* proj_b   = (const float*)d_in[6];
    const float* proj_la  = (const float*)d_in[7];
    const float* proj_lb  = (const float*)d_in[8];
    const float* fc1_w    = (const float*)d_in[9];
    const float* fc1_b    = (const float*)d_in[10];
    const float* fc1_la   = (const float*)d_in[11];
    const float* fc1_lb   = (const float*)d_in[12];
    const float* fc2_w    = (const float*)d_in[13];
    const float* fc2_b    = (const float*)d_in[14];
    const float* fc2_la   = (const float*)d_in[15];
    const float* fc2_lb   = (const float*)d_in[16];
    float* out = (float*)d_out;

    float *qkv, *xo, *h, *xo2, *a2;
    cudaGetSymbolAddress((void**)&qkv, g_qkv);
    cudaGetSymbolAddress((void**)&xo,  g_xo);
    cudaGetSymbolAddress((void**)&h,   g_h);
    cudaGetSymbolAddress((void**)&xo2, g_xo2);
    cudaGetSymbolAddress((void**)&a2,  g_a2);

    __nv_bfloat16 *ah,*al,*ah2,*al2,*a2h,*a2l;
    __nv_bfloat16 *wqh,*wql,*w1h,*w1l,*w2h,*w2l,*wph,*wpl;
    __nv_bfloat16 *lqh,*lql,*l1h,*l1l,*l2h,*l2l,*lph,*lpl;
    cudaGetSymbolAddress((void**)&ah,  g_ah);   cudaGetSymbolAddress((void**)&al,  g_al);
    cudaGetSymbolAddress((void**)&ah2, g_ah2);  cudaGetSymbolAddress((void**)&al2, g_al2);
    cudaGetSymbolAddress((void**)&a2h, g_a2h);  cudaGetSymbolAddress((void**)&a2l, g_a2l);
    cudaGetSymbolAddress((void**)&wqh, g_wqkv_h); cudaGetSymbolAddress((void**)&wql, g_wqkv_l);
    cudaGetSymbolAddress((void**)&w1h, g_wfc1_h); cudaGetSymbolAddress((void**)&w1l, g_wfc1_l);
    cudaGetSymbolAddress((void**)&w2h, g_wfc2_h); cudaGetSymbolAddress((void**)&w2l, g_wfc2_l);
    cudaGetSymbolAddress((void**)&wph, g_wproj_h); cudaGetSymbolAddress((void**)&wpl, g_wproj_l);
    cudaGetSymbolAddress((void**)&lqh, g_lbqkv_h); cudaGetSymbolAddress((void**)&lql, g_lbqkv_l);
    cudaGetSymbolAddress((void**)&l1h, g_lbfc1_h); cudaGetSymbolAddress((void**)&l1l, g_lbfc1_l);
    cudaGetSymbolAddress((void**)&l2h, g_lbfc2_h); cudaGetSymbolAddress((void**)&l2l, g_lbfc2_l);
    cudaGetSymbolAddress((void**)&lph, g_lbproj_h); cudaGetSymbolAddress((void**)&lpl, g_lbproj_l);

    cudaFuncSetAttribute(mm_gemm_kernel,
                         cudaFuncAttributeMaxDynamicSharedMemorySize, DSMB);

    const int M = MTOT;
    const int actN4 = M * CC / 4;
    const int a2N4  = M * RR / 4;

    // ---- weight prep ----
    transpose_convert_kernel<<<dim3(3*CC/32, CC/32), 256>>>(qkv_w, wqh, wql, CC, 3*CC);
    transpose_convert_kernel<<<dim3(CC/32,  CC/32), 256>>>(fc1_w, w1h, w1l, CC, CC);
    transpose_convert_kernel<<<dim3(CC/32,  CC/32), 256>>>(fc2_w, w2h, w2l, CC, CC);
    transpose_convert_kernel<<<dim3(CC/32,  CC/32), 256>>>(proj_w, wph, wpl, CC, CC);
    transpose_convert_kernel<<<dim3(3*CC/32, 1), 256>>>(qkv_lb, lqh, lql, RR, 3*CC);
    transpose_convert_kernel<<<dim3(CC/32, 1), 256>>>(fc1_lb, l1h, l1l, RR, CC);
    transpose_convert_kernel<<<dim3(CC/32, 1), 256>>>(fc2_lb, l2h, l2l, RR, CC);
    transpose_convert_kernel<<<dim3(CC/32, 1), 256>>>(proj_lb, lph, lpl, RR, CC);

    // ---- qkv: A = x (ah/al), out fp32 only ----
    gemm_la_kernel<<<M/32, 256>>>(x, qkv_la, a2, CC);
    convert_hilo_kernel<<<actN4/256, 256>>>(x, ah, al, actN4);
    convert_hilo_kernel<<<a2N4/256, 256>>>(a2, a2h, a2l, a2N4);
    mm_gemm_kernel<<<dim3(3*CC/128, M/128), 256, DSMB>>>(
        ah, al, a2h, a2l, wqh, wql, lqh, lql, qkv, nullptr, nullptr,
        nullptr, nullptr, 0, 3*CC);

    // ---- attention -> xo fp32 + ah/al (xo hi/lo; x copies dead now) ----
    attn_kernel<<<dim3(SS/128, BB*HH), 128>>>(qkv, mask, xo, ah, al);

    // ---- fc1: A = xo (ah/al), out h fp32 + ah2/al2 ----
    gemm_la_kernel<<<M/32, 256>>>(xo, fc1_la, a2, CC);
    convert_hilo_kernel<<<a2N4/256, 256>>>(a2, a2h, a2l, a2N4);
    mm_gemm_kernel<<<dim3(CC/128, M/128), 256, DSMB>>>(
        ah, al, a2h, a2l, w1h, w1l, l1h, l1l, h, ah2, al2, fc1_b, nullptr, 1, CC);

    // ---- fc2: A = h (ah2/al2), out xo2 fp32 + ah/al (+res xo) ----
    gemm_la_kernel<<<M/32, 256>>>(h, fc2_la, a2, CC);
    convert_hilo_kernel<<<a2N4/256, 256>>>(a2, a2h, a2l, a2N4);
    mm_gemm_kernel<<<dim3(CC/128, M/128), 256, DSMB>>>(
        ah2, al2, a2h, a2l, w2h, w2l, l2h, l2l, xo2, ah, al, fc2_b, xo, 0, CC);

    // ---- proj: A = xo2 (ah/al), out -> d_out fp32 ----
    gemm_la_kernel<<<M/32, 256>>>(xo2, proj_la, a2, CC);
    convert_hilo_kernel<<<a2N4/256, 256>>>(a2, a2h, a2l, a2N4);
    mm_gemm_kernel<<<dim3(CC/128, M/128), 256, DSMB>>>(
        ah, al, a2h, a2l, wph, wpl, lph, lpl, out, nullptr, nullptr,
        proj_b, nullptr, 0, CC);
}

// round 11
// speedup vs baseline: 2.6719x; 1.2236x over previous
#include <cuda_runtime.h>
#include <cuda_bf16.h>
#include <math.h>
#include <stdint.h>

#define BB 8
#define SS 512
#define CC 1024
#define HH 16
#define RR 32
#define MTOT (BB*SS)          // 4096
#define KK CC                 // GEMM K = 1024

// ---------------- fp32 scratch ----------------------------------------------
__device__ float g_xo [MTOT * CC];
__device__ float g_h  [MTOT * CC];
__device__ float g_xo2[MTOT * CC];
__device__ float g_a2 [MTOT * RR];

// ---------------- bf16 hi/lo scratch ----------------------------------------
__device__ __nv_bfloat16 g_qkvh[MTOT * 3 * CC], g_qkvl[MTOT * 3 * CC];
__device__ __nv_bfloat16 g_ah [MTOT * CC], g_al [MTOT * CC];   // buffer pair A
__device__ __nv_bfloat16 g_ah2[MTOT * CC], g_al2[MTOT * CC];   // buffer pair B
__device__ __nv_bfloat16 g_a2h[MTOT * RR], g_a2l[MTOT * RR];
__device__ __nv_bfloat16 g_wqkv_h[3*CC*CC], g_wqkv_l[3*CC*CC]; // [N,K]
__device__ __nv_bfloat16 g_wfc1_h[CC*CC],  g_wfc1_l[CC*CC];
__device__ __nv_bfloat16 g_wfc2_h[CC*CC],  g_wfc2_l[CC*CC];
__device__ __nv_bfloat16 g_wproj_h[CC*CC], g_wproj_l[CC*CC];
__device__ __nv_bfloat16 g_lbqkv_h[3*CC*RR], g_lbqkv_l[3*CC*RR];
__device__ __nv_bfloat16 g_lbfc1_h[CC*RR], g_lbfc1_l[CC*RR];
__device__ __nv_bfloat16 g_lbfc2_h[CC*RR], g_lbfc2_l[CC*RR];
__device__ __nv_bfloat16 g_lbproj_h[CC*RR], g_lbproj_l[CC*RR];

// ---------------- helpers ----------------------------------------------------
__device__ __forceinline__ float gelu_exact(float x) {
    return 0.5f * x * (1.0f + erff(x * 0.70710678118654752440f));
}
__device__ __forceinline__ void mma_bf16(float* c, const uint32_t* a,
                                         uint32_t b0, uint32_t b1) {
    asm volatile(
        "mma.sync.aligned.m16n8k16.row.col.f32.bf16.bf16.f32 "
        "{%0,%1,%2,%3}, {%4,%5,%6,%7}, {%8,%9}, {%0,%1,%2,%3};"
        : "+f"(c[0]), "+f"(c[1]), "+f"(c[2]), "+f"(c[3])
        : "r"(a[0]), "r"(a[1]), "r"(a[2]), "r"(a[3]), "r"(b0), "r"(b1));
}
__device__ __forceinline__ void ldsm4(uint32_t* r, uint32_t addr) {
    asm volatile("ldmatrix.sync.aligned.m8n8.x4.shared.b16 {%0,%1,%2,%3}, [%4];"
        : "=r"(r[0]), "=r"(r[1]), "=r"(r[2]), "=r"(r[3]) : "r"(addr));
}
__device__ __forceinline__ void ldsm4t(uint32_t* r, uint32_t addr) {
    asm volatile("ldmatrix.sync.aligned.m8n8.x4.trans.shared.b16 {%0,%1,%2,%3}, [%4];"
        : "=r"(r[0]), "=r"(r[1]), "=r"(r[2]), "=r"(r[3]) : "r"(addr));
}
#define CP_ASYNC16(dst_u32, src_ptr) \
    asm volatile("cp.async.cg.shared.global [%0], [%1], 16;" \
                 :: "r"(dst_u32), "l"(src_ptr))
#define CP_COMMIT() asm volatile("cp.async.commit_group;" ::: "memory")

__device__ __forceinline__ uint32_t packbf(float x, float y) {
    __nv_bfloat162 t = __halves2bfloat162(__float2bfloat16_rn(x),
                                          __float2bfloat16_rn(y));
    return *(uint32_t*)&t;
}

// ---------------- HMMA bf16x3 GEMM -------------------------------------------
#define TCSTRIDE 80
#define MATB 10240
#define STAGEB (4*MATB)
#define DSMB (2*STAGEB)

__global__ __launch_bounds__(256, 2) void mm_gemm_kernel(
    const __nv_bfloat16* __restrict__ Ah,  const __nv_bfloat16* __restrict__ Al,
    const __nv_bfloat16* __restrict__ A2h, const __nv_bfloat16* __restrict__ A2l,
    const __nv_bfloat16* __restrict__ Bh,  const __nv_bfloat16* __restrict__ Bl,
    const __nv_bfloat16* __restrict__ LBh, const __nv_bfloat16* __restrict__ LBl,
    float* __restrict__ C, __nv_bfloat16* __restrict__ Ch,
    __nv_bfloat16* __restrict__ Cl, const float* __restrict__ bias,
    const float* __restrict__ res, int act, int N)
{
    extern __shared__ char dsm[];
    const int tid = threadIdx.x;
    const int row0 = blockIdx.y * 128;
    const int col0 = blockIdx.x * 128;
    const int w = tid >> 5, lane = tid & 31;
    const int gid = lane >> 2, t4 = lane & 3;
    const int wm = (w & 3) * 32, wn = (w >> 2) * 64;

    const uint32_t smem0 = (uint32_t)__cvta_generic_to_shared(dsm);

    const int a_r  = (lane & 15);
    const int a_ko = (lane >> 4) * 16;
    const int b_r  = (lane & 7) + ((lane >> 4) << 3);
    const int b_ko = ((lane >> 3) & 1) * 16;

    float acc[2][8][4];
#pragma unroll
    for (int i = 0; i < 2; i++)
#pragma unroll
        for (int j = 0; j < 8; j++)
#pragma unroll
            for (int r = 0; r < 4; r++) acc[i][j][r] = 0.f;

    auto load_stage = [&](int buf, int kc) {
        const uint32_t sb = smem0 + buf * STAGEB;
        const bool lora = (kc == 32);
        const int koff = lora ? 0 : kc * 32;
        const int strd = lora ? RR : KK;
        const __nv_bfloat16* p0 = lora ? A2h : Ah;
        const __nv_bfloat16* p1 = lora ? A2l : Al;
        const __nv_bfloat16* p2 = lora ? LBh : Bh;
        const __nv_bfloat16* p3 = lora ? LBl : Bl;
#pragma unroll
        for (int t = 0; t < 8; t++) {
            const int idx = tid + t * 256;
            const int m = idx >> 9;
            const int r = (idx >> 2) & 127;
            const int q = idx & 3;
            const __nv_bfloat16* base =
                (m == 0) ? p0 : (m == 1) ? p1 : (m == 2) ? p2 : p3;
            const int grow = ((m < 2) ? row0 : col0) + r;
            const __nv_bfloat16* src = base + (size_t)grow * strd + koff + q * 8;
            const uint32_t dst = sb + m * MATB + r * TCSTRIDE + q * 16;
            CP_ASYNC16(dst, src);
        }
        CP_COMMIT();
    };

    auto compute = [&](int buf) {
        const uint32_t sb = smem0 + buf * STAGEB;
#pragma unroll
        for (int ks = 0; ks < 2; ks++) {
            const int kb = ks * 32;
            uint32_t a[2][2][4];
#pragma unroll
            for (int i = 0; i < 2; i++) {
                const uint32_t ra = (wm + i * 16 + a_r) * TCSTRIDE + kb + a_ko;
                ldsm4(a[i][0], sb + ra);
                ldsm4(a[i][1], sb + MATB + ra);
            }
#pragma unroll
            for (int jp = 0; jp < 4; jp++) {
                uint32_t bh[4], bl[4];
                const uint32_t rb = (wn + jp * 16 + b_r) * TCSTRIDE + kb + b_ko;
                ldsm4(bh, sb + 2 * MATB + rb);
                ldsm4(bl, sb + 3 * MATB + rb);
#pragma unroll
                for (int i = 0; i < 2; i++) {
                    mma_bf16(acc[i][2*jp],   a[i][0], bh[0], bh[1]);
                    mma_bf16(acc[i][2*jp],   a[i][0], bl[0], bl[1]);
                    mma_bf16(acc[i][2*jp],   a[i][1], bh[0], bh[1]);
                    mma_bf16(acc[i][2*jp+1], a[i][0], bh[2], bh[3]);
                    mma_bf16(acc[i][2*jp+1], a[i][0], bl[2], bl[3]);
                    mma_bf16(acc[i][2*jp+1], a[i][1], bh[2], bh[3]);
                }
            }
        }
    };

    load_stage(0, 0);
    for (int kc = 0; kc < 33; kc++) {
        if (kc + 1 < 33) {
            load_stage((kc + 1) & 1, kc + 1);
            asm volatile("cp.async.wait_group 1;" ::: "memory");
        } else {
            asm volatile("cp.async.wait_group 0;" ::: "memory");
        }
        __syncthreads();
        compute(kc & 1);
        __syncthreads();
    }

#pragma unroll
    for (int i = 0; i < 2; i++) {
        const int r0 = row0 + wm + i * 16 + gid;
#pragma unroll
        for (int j = 0; j < 8; j++) {
            const int col = col0 + wn + j * 8 + t4 * 2;
            float v0 = acc[i][j][0], v1 = acc[i][j][1];
            float v2 = acc[i][j][2], v3 = acc[i][j][3];
            if (bias) {
                const float b0 = bias[col], b1 = bias[col + 1];
                v0 += b0; v1 += b1; v2 += b0; v3 += b1;
            }
            if (act) {
                v0 = gelu_exact(v0); v1 = gelu_exact(v1);
                v2 = gelu_exact(v2); v3 = gelu_exact(v3);
            }
            if (res) {
                const float* rp0 = res + (size_t)r0 * N + col;
                const float* rp1 = res + (size_t)(r0 + 8) * N + col;
                v0 += rp0[0]; v1 += rp0[1]; v2 += rp1[0]; v3 += rp1[1];
            }
            if (C) {
                *(float2*)(C + (size_t)r0 * N + col) = make_float2(v0, v1);
                *(float2*)(C + (size_t)(r0 + 8) * N + col) = make_float2(v2, v3);
            }
            if (Ch) {
                const __nv_bfloat16 h0 = __float2bfloat16_rn(v0);
                const __nv_bfloat16 h1 = __float2bfloat16_rn(v1);
                const __nv_bfloat16 h2 = __float2bfloat16_rn(v2);
                const __nv_bfloat16 h3 = __float2bfloat16_rn(v3);
                *(__nv_bfloat162*)(Ch + (size_t)r0 * N + col) =
                    __halves2bfloat162(h0, h1);
                *(__nv_bfloat162*)(Ch + (size_t)(r0 + 8) * N + col) =
                    __halves2bfloat162(h2, h3);
                *(__nv_bfloat162*)(Cl + (size_t)r0 * N + col) =
                    __halves2bfloat162(__float2bfloat16_rn(v0 - __bfloat162float(h0)),
                                       __float2bfloat16_rn(v1 - __bfloat162float(h1)));
                *(__nv_bfloat162*)(Cl + (size_t)(r0 + 8) * N + col) =
                    __halves2bfloat162(__float2bfloat16_rn(v2 - __bfloat162float(h2)),
                                       __float2bfloat16_rn(v3 - __bfloat162float(h3)));
            }
        }
    }
}

// ---------------- prep kernels ----------------------------------------------
__global__ __launch_bounds__(256) void transpose_convert_kernel(
    const float* __restrict__ W, __nv_bfloat16* __restrict__ Th,
    __nv_bfloat16* __restrict__ Tl, int K, int N)
{
    __shared__ float s[32][33];
    const int tx = threadIdx.x & 31, ty = threadIdx.x >> 5;
    const int n0 = blockIdx.x * 32, k0 = blockIdx.y * 32;
#pragma unroll
    for (int i = 0; i < 4; i++)
        s[ty + 8*i][tx] = W[(size_t)(k0 + ty + 8*i) * N + n0 + tx];
    __syncthreads();
#pragma unroll
    for (int i = 0; i < 4; i++) {
        const int n = ty + 8*i;
        const float v = s[tx][n];
        const __nv_bfloat16 h = __float2bfloat16_rn(v);
        const __nv_bfloat16 l = __float2bfloat16_rn(v - __bfloat162float(h));
        const size_t o = (size_t)(n0 + n) * K + k0 + tx;
        Th[o] = h; Tl[o] = l;
    }
}

__global__ __launch_bounds__(256) void convert_hilo_kernel(
    const float* __restrict__ in, __nv_bfloat16* __restrict__ oh,
    __nv_bfloat16* __restrict__ ol, int n4)
{
    const int i = blockIdx.x * 256 + threadIdx.x;
    if (i >= n4) return;
    const float4 v = ((const float4*)in)[i];
    const __nv_bfloat16 hx = __float2bfloat16_rn(v.x);
    const __nv_bfloat16 hy = __float2bfloat16_rn(v.y);
    const __nv_bfloat16 hz = __float2bfloat16_rn(v.z);
    const __nv_bfloat16 hw = __float2bfloat16_rn(v.w);
    ((__nv_bfloat162*)oh)[2*i]   = __halves2bfloat162(hx, hy);
    ((__nv_bfloat162*)oh)[2*i+1] = __halves2bfloat162(hz, hw);
    ((__nv_bfloat162*)ol)[2*i]   = __halves2bfloat162(
        __float2bfloat16_rn(v.x - __bfloat162float(hx)),
        __float2bfloat16_rn(v.y - __bfloat162float(hy)));
    ((__nv_bfloat162*)ol)[2*i+1] = __halves2bfloat162(
        __float2bfloat16_rn(v.z - __bfloat162float(hz)),
        __float2bfloat16_rn(v.w - __bfloat162float(hw)));
}

// ---------------- LoRA A-projection ------------------------------------------
__global__ __launch_bounds__(256) void gemm_la_kernel(
    const float* __restrict__ A, const float* __restrict__ LA,
    float* __restrict__ A2, int K)
{
    __shared__ float sA[32 * 32];
    __shared__ float sLAt[32 * 36];
    const int tid = threadIdx.x;
    const int row0 = blockIdx.x * 32;
    const int col = tid & 31;
    const int rgrp = tid >> 5;

    float s[4] = {0.f, 0.f, 0.f, 0.f};

    for (int k0 = 0; k0 < K; k0 += 32) {
        __syncthreads();
        {
            const int r = tid >> 3, c = (tid & 7) * 4;
            *(float4*)&sA[r * 32 + c] =
                *(const float4*)(A + (size_t)(row0 + r) * K + k0 + c);
        }
#pragma unroll
        for (int t = 0; t < 4; t++) {
            const int idx = tid + t * 256;
            const int kk = idx >> 5, c = idx & 31;
            sLAt[c * 36 + kk] = LA[(size_t)(k0 + kk) * 32 + c];
        }
        __syncthreads();
#pragma unroll
        for (int kk = 0; kk < 32; kk += 4) {
            const float4 la = *(const float4*)&sLAt[col * 36 + kk];
#pragma unroll
            for (int rr = 0; rr < 4; rr++) {
                const float4 a = *(const float4*)&sA[(rgrp + rr * 8) * 32 + kk];
                s[rr] += a.x * la.x + a.y * la.y + a.z * la.z + a.w * la.w;
            }
        }
    }
#pragma unroll
    for (int rr = 0; rr < 4; rr++)
        A2[(size_t)(row0 + rgrp + rr * 8) * 32 + col] = s[rr];
}

// ---------------- tensor-core flash attention --------------------------------
// grid (4, 128), 256 threads (8 warps). Q block 128 rows, key tiles of 64.
#define ATSTR 144              // smem row stride bytes (64 bf16 + pad)
#define ATT_QB (128*ATSTR)     // 18432
#define ATT_T  (64*ATSTR)      // 9216
#define ATT_BUF (4*ATT_T)      // 36864
#define ATT_SMEM (2*ATT_QB + 2*ATT_BUF + 512)

__global__ __launch_bounds__(256, 1) void attn_mma_kernel(
    const __nv_bfloat16* __restrict__ qkvh,
    const __nv_bfloat16* __restrict__ qkvl,
    const int* __restrict__ mask,
    float* __restrict__ xo, __nv_bfloat16* __restrict__ xoh,
    __nv_bfloat16* __restrict__ xol)
{
    extern __shared__ char dsm[];
    const int tid = threadIdx.x;
    const int w = tid >> 5, lane = tid & 31;
    const int gid = lane >> 2, t4 = lane & 3;
    const int bh = blockIdx.y, b = bh >> 4, h = bh & 15;
    const int qblk = blockIdx.x * 128;

    const uint32_t s0 = (uint32_t)__cvta_generic_to_shared(dsm);
    const uint32_t sQ = s0;                          // Qh, Ql
    const uint32_t sKV = s0 + 2 * ATT_QB;            // 2 buffers x (Kh,Kl,Vh,Vl)
    const uint32_t sMk = sKV + 2 * ATT_BUF;          // 2 x 256B mask

    const int a_r = lane & 15, a_ko = (lane >> 4) * 16;
    const int b_r = (lane & 7) + ((lane >> 4) << 3);
    const int b_ko = ((lane >> 3) & 1) * 16;

    // ---- group 0: Q (hi+lo) + tile 0 ----
#pragma unroll
    for (int t = 0; t < 8; t++) {
        const int idx = tid + t * 256;               // 0..2047
        const int m = idx >> 10;                     // 0=Qh 1=Ql
        const int r = (idx >> 3) & 127;
        const int q = idx & 7;
        const __nv_bfloat16* src = (m ? qkvl : qkvh)
            + (size_t)(b * SS + qblk + r) * 3072 + h * 64 + q * 8;
        CP_ASYNC16(sQ + m * ATT_QB + r * ATSTR + q * 16, src);
    }
    auto load_tile = [&](int kt, int buf) {
#pragma unroll
        for (int t = 0; t < 8; t++) {
            const int idx = tid + t * 256;
            const int m = idx >> 9;                  // 0=Kh 1=Kl 2=Vh 3=Vl
            const int r = (idx >> 3) & 63;
            const int q = idx & 7;
            const int colb = ((m < 2) ? 1024 : 2048) + h * 64;
            const __nv_bfloat16* src = ((m & 1) ? qkvl : qkvh)
                + (size_t)(b * SS + kt * 64 + r) * 3072 + colb + q * 8;
            CP_ASYNC16(sKV + buf * ATT_BUF + m * ATT_T + r * ATSTR + q * 16, src);
        }
        if (tid < 16)
            CP_ASYNC16(sMk + buf * 256 + tid * 16,
                       mask + (size_t)b * (3 * SS) + kt * 64 + tid * 4);
        CP_COMMIT();
    };
    load_tile(0, 0);
    CP_COMMIT();   // group boundary (Q+tile0 committed inside load_tile already; extra empty group harmless)

    float o[8][4];
#pragma unroll
    for (int j = 0; j < 8; j++)
#pragma unroll
        for (int r = 0; r < 4; r++) o[j][r] = 0.f;
    float mr0 = -INFINITY, mr1 = -INFINITY, l0 = 0.f, l1 = 0.f;

    for (int kt = 0; kt < 8; kt++) {
        const int buf = kt & 1;
        if (kt < 7) {
            load_tile(kt + 1, buf ^ 1);
            asm volatile("cp.async.wait_group 1;" ::: "memory");
        } else {
            asm volatile("cp.async.wait_group 0;" ::: "memory");
        }
        __syncthreads();

        const uint32_t kB = sKV + buf * ATT_BUF;
        const int* msk = (const int*)(dsm + (2 * ATT_QB + 2 * ATT_BUF) + buf * 256);

        // ---- scores S = Qh*Kh + Qh*Kl + Ql*Kh ----
        float s[8][4];
#pragma unroll
        for (int j = 0; j < 8; j++)
#pragma unroll
            for (int r = 0; r < 4; r++) s[j][r] = 0.f;
#pragma unroll
        for (int ks = 0; ks < 4; ks++) {
            uint32_t qh[4], ql[4];
            const uint32_t qa = sQ + (w * 16 + a_r) * ATSTR + ks * 32 + a_ko;
            ldsm4(qh, qa);
            ldsm4(ql, qa + ATT_QB);
#pragma unroll
            for (int jp = 0; jp < 4; jp++) {
                uint32_t bh4[4], bl4[4];
                const uint32_t ba = kB + (jp * 16 + b_r) * ATSTR + ks * 32 + b_ko;
                ldsm4(bh4, ba);
                ldsm4(bl4, ba + ATT_T);
                mma_bf16(s[2*jp],   qh, bh4[0], bh4[1]);
                mma_bf16(s[2*jp],   qh, bl4[0], bl4[1]);
                mma_bf16(s[2*jp],   ql, bh4[0], bh4[1]);
                mma_bf16(s[2*jp+1], qh, bh4[2], bh4[3]);
                mma_bf16(s[2*jp+1], qh, bl4[2], bl4[3]);
                mma_bf16(s[2*jp+1], ql, bh4[2], bh4[3]);
            }
        }

        // ---- online softmax in fragments ----
        float tm0 = -INFINITY, tm1 = -INFINITY;
#pragma unroll
        for (int j = 0; j < 8; j++) {
            const int c0 = 8 * j + 2 * t4;
            const bool v0 = msk[c0] != 0, v1 = msk[c0 + 1] != 0;
            s[j][0] = v0 ? s[j][0] * 0.125f : -INFINITY;
            s[j][1] = v1 ? s[j][1] * 0.125f : -INFINITY;
            s[j][2] = v0 ? s[j][2] * 0.125f : -INFINITY;
            s[j][3] = v1 ? s[j][3] * 0.125f : -INFINITY;
            tm0 = fmaxf(tm0, fmaxf(s[j][0], s[j][1]));
            tm1 = fmaxf(tm1, fmaxf(s[j][2], s[j][3]));
        }
        tm0 = fmaxf(tm0, __shfl_xor_sync(0xffffffffu, tm0, 1));
        tm0 = fmaxf(tm0, __shfl_xor_sync(0xffffffffu, tm0, 2));
        tm1 = fmaxf(tm1, __shfl_xor_sync(0xffffffffu, tm1, 1));
        tm1 = fmaxf(tm1, __shfl_xor_sync(0xffffffffu, tm1, 2));
        const float nm0 = fmaxf(mr0, tm0), nm1 = fmaxf(mr1, tm1);
        const float nb0 = (nm0 == -INFINITY) ? 0.f : nm0;   // safe subtrahend
        const float nb1 = (nm1 == -INFINITY) ? 0.f : nm1;
        const float cr0 = __expf(mr0 - nb0), cr1 = __expf(mr1 - nb1);
        float sum0 = 0.f, sum1 = 0.f;
#pragma unroll
        for (int j = 0; j < 8; j++) {
            s[j][0] = __expf(s[j][0] - nb0);
            s[j][1] = __expf(s[j][1] - nb0);
            s[j][2] = __expf(s[j][2] - nb1);
            s[j][3] = __expf(s[j][3] - nb1);
            sum0 += s[j][0] + s[j][1];
            sum1 += s[j][2] + s[j][3];
            o[j][0] *= cr0; o[j][1] *= cr0;
            o[j][2] *= cr1; o[j][3] *= cr1;
        }
        sum0 += __shfl_xor_sync(0xffffffffu, sum0, 1);
        sum0 += __shfl_xor_sync(0xffffffffu, sum0, 2);
        sum1 += __shfl_xor_sync(0xffffffffu, sum1, 1);
        sum1 += __shfl_xor_sync(0xffffffffu, sum1, 2);
        l0 = l0 * cr0 + sum0;
        l1 = l1 * cr1 + sum1;
        mr0 = nm0; mr1 = nm1;

        // ---- O += P*V  (Ph*Vh + Ph*Vl + Pl*Vh) ----
#pragma unroll
        for (int kt2 = 0; kt2 < 4; kt2++) {
            uint32_t pah[4], pal[4];
            {
                const float* pj0 = s[2 * kt2];
                const float* pj1 = s[2 * kt2 + 1];
                pah[0] = packbf(pj0[0], pj0[1]);
                pah[1] = packbf(pj0[2], pj0[3]);
                pah[2] = packbf(pj1[0], pj1[1]);
                pah[3] = packbf(pj1[2], pj1[3]);
                const __nv_bfloat162* h0 = (const __nv_bfloat162*)&pah[0];
                pal[0] = packbf(pj0[0] - __bfloat162float(h0[0].x),
                                pj0[1] - __bfloat162float(h0[0].y));
                const __nv_bfloat162* h1 = (const __nv_bfloat162*)&pah[1];
                pal[1] = packbf(pj0[2] - __bfloat162float(h1[0].x),
                                pj0[3] - __bfloat162float(h1[0].y));
                const __nv_bfloat162* h2 = (const __nv_bfloat162*)&pah[2];
                pal[2] = packbf(pj1[0] - __bfloat162float(h2[0].x),
                                pj1[1] - __bfloat162float(h2[0].y));
                const __nv_bfloat162* h3 = (const __nv_bfloat162*)&pah[3];
                pal[3] = packbf(pj1[2] - __bfloat162float(h3[0].x),
                                pj1[3] - __bfloat162float(h3[0].y));
            }
#pragma unroll
            for (int jp = 0; jp < 4; jp++) {
                uint32_t vh4[4], vl4[4];
                const uint32_t va = kB + 2 * ATT_T
                    + (kt2 * 16 + a_r) * ATSTR + jp * 32 + a_ko;
                ldsm4t(vh4, va);
                ldsm4t(vl4, va + ATT_T);
                mma_bf16(o[2*jp],   pah, vh4[0], vh4[1]);
                mma_bf16(o[2*jp],   pah, vl4[0], vl4[1]);
                mma_bf16(o[2*jp],   pal, vh4[0], vh4[1]);
                mma_bf16(o[2*jp+1], pah, vh4[2], vh4[3]);
                mma_bf16(o[2*jp+1], pah, vl4[2], vl4[3]);
                mma_bf16(o[2*jp+1], pal, vh4[2], vh4[3]);
            }
        }
        __syncthreads();
    }

    // ---- normalize + write ----
    const float inv0 = (l0 > 0.f) ? (1.f / l0) : 0.f;
    const float inv1 = (l1 > 0.f) ? (1.f / l1) : 0.f;
    const size_t ob0 = (size_t)(b * SS + qblk + w * 16 + gid) * CC + h * 64;
    const size_t ob1 = ob0 + (size_t)8 * CC;
#pragma unroll
    for (int j = 0; j < 8; j++) {
        const int col = 8 * j + 2 * t4;
        const float v0 = o[j][0] * inv0, v1 = o[j][1] * inv0;
        const float v2 = o[j][2] * inv1, v3 = o[j][3] * inv1;
        *(float2*)(xo + ob0 + col) = make_float2(v0, v1);
        *(float2*)(xo + ob1 + col) = make_float2(v2, v3);
        const __nv_bfloat16 h0 = __float2bfloat16_rn(v0);
        const __nv_bfloat16 h1 = __float2bfloat16_rn(v1);
        const __nv_bfloat16 h2 = __float2bfloat16_rn(v2);
        const __nv_bfloat16 h3 = __float2bfloat16_rn(v3);
        *(__nv_bfloat162*)(xoh + ob0 + col) = __halves2bfloat162(h0, h1);
        *(__nv_bfloat162*)(xoh + ob1 + col) = __halves2bfloat162(h2, h3);
        *(__nv_bfloat162*)(xol + ob0 + col) = __halves2bfloat162(
            __float2bfloat16_rn(v0 - __bfloat162float(h0)),
            __float2bfloat16_rn(v1 - __bfloat162float(h1)));
        *(__nv_bfloat162*)(xol + ob1 + col) = __halves2bfloat162(
            __float2bfloat16_rn(v2 - __bfloat162float(h2)),
            __float2bfloat16_rn(v3 - __bfloat162float(h3)));
    }
}

// ---------------- launch -----------------------------------------------------
extern "C" void kernel_launch(void* const* d_in, const int* in_sizes, int n_in,
                              void* d_out, int out_size)
{
    const float* x        = (const float*)d_in[0];
    const int*   mask     = (const int*)d_in[1];
    const float* qkv_w    = (const float*)d_in[2];
    const float* qkv_la   = (const float*)d_in[3];
    const float* qkv_lb   = (const float*)d_in[4];
    const float* proj_w   = (const float*)d_in[5];
    const float* proj_b   = (const float*)d_in[6];
    const float* proj_la  = (const float*)d_in[7];
    const float* proj_lb  = (const float*)d_in[8];
    const float* fc1_w    = (const float*)d_in[9];
    const float* fc1_b    = (const float*)d_in[10];
    const float* fc1_la   = (const float*)d_in[11];
    const float* fc1_lb   = (const float*)d_in[12];
    const float* fc2_w    = (const float*)d_in[13];
    const float* fc2_b    = (const float*)d_in[14];
    const float* fc2_la   = (const float*)d_in[15];
    const float* fc2_lb   = (const float*)d_in[16];
    float* out = (float*)d_out;

    float *xo, *hbuf, *xo2, *a2;
    cudaGetSymbolAddress((void**)&xo,  g_xo);
    cudaGetSymbolAddress((void**)&hbuf, g_h);
    cudaGetSymbolAddress((void**)&xo2, g_xo2);
    cudaGetSymbolAddress((void**)&a2,  g_a2);

    __nv_bfloat16 *qkvh,*qkvl,*ah,*al,*ah2,*al2,*a2h,*a2l;
    __nv_bfloat16 *wqh,*wql,*w1h,*w1l,*w2h,*w2l,*wph,*wpl;
    __nv_bfloat16 *lqh,*lql,*l1h,*l1l,*l2h,*l2l,*lph,*lpl;
    cudaGetSymbolAddress((void**)&qkvh, g_qkvh); cudaGetSymbolAddress((void**)&qkvl, g_qkvl);
    cudaGetSymbolAddress((void**)&ah,  g_ah);   cudaGetSymbolAddress((void**)&al,  g_al);
    cudaGetSymbolAddress((void**)&ah2, g_ah2);  cudaGetSymbolAddress((void**)&al2, g_al2);
    cudaGetSymbolAddress((void**)&a2h, g_a2h);  cudaGetSymbolAddress((void**)&a2l, g_a2l);
    cudaGetSymbolAddress((void**)&wqh, g_wqkv_h); cudaGetSymbolAddress((void**)&wql, g_wqkv_l);
    cudaGetSymbolAddress((void**)&w1h, g_wfc1_h); cudaGetSymbolAddress((void**)&w1l, g_wfc1_l);
    cudaGetSymbolAddress((void**)&w2h, g_wfc2_h); cudaGetSymbolAddress((void**)&w2l, g_wfc2_l);
    cudaGetSymbolAddress((void**)&wph, g_wproj_h); cudaGetSymbolAddress((void**)&wpl, g_wproj_l);
    cudaGetSymbolAddress((void**)&lqh, g_lbqkv_h); cudaGetSymbolAddress((void**)&lql, g_lbqkv_l);
    cudaGetSymbolAddress((void**)&l1h, g_lbfc1_h); cudaGetSymbolAddress((void**)&l1l, g_lbfc1_l);
    cudaGetSymbolAddress((void**)&l2h, g_lbfc2_h); cudaGetSymbolAddress((void**)&l2l, g_lbfc2_l);
    cudaGetSymbolAddress((void**)&lph, g_lbproj_h); cudaGetSymbolAddress((void**)&lpl, g_lbproj_l);

    cudaFuncSetAttribute(mm_gemm_kernel,
                         cudaFuncAttributeMaxDynamicSharedMemorySize, DSMB);
    cudaFuncSetAttribute(attn_mma_kernel,
                         cudaFuncAttributeMaxDynamicSharedMemorySize, ATT_SMEM);

    const int M = MTOT;
    const int actN4 = M * CC / 4;
    const int a2N4  = M * RR / 4;

    // ---- weight prep ----
    transpose_convert_kernel<<<dim3(3*CC/32, CC/32), 256>>>(qkv_w, wqh, wql, CC, 3*CC);
    transpose_convert_kernel<<<dim3(CC/32,  CC/32), 256>>>(fc1_w, w1h, w1l, CC, CC);
    transpose_convert_kernel<<<dim3(CC/32,  CC/32), 256>>>(fc2_w, w2h, w2l, CC, CC);
    transpose_convert_kernel<<<dim3(CC/32,  CC/32), 256>>>(proj_w, wph, wpl, CC, CC);
    transpose_convert_kernel<<<dim3(3*CC/32, 1), 256>>>(qkv_lb, lqh, lql, RR, 3*CC);
    transpose_convert_kernel<<<dim3(CC/32, 1), 256>>>(fc1_lb, l1h, l1l, RR, CC);
    transpose_convert_kernel<<<dim3(CC/32, 1), 256>>>(fc2_lb, l2h, l2l, RR, CC);
    transpose_convert_kernel<<<dim3(CC/32, 1), 256>>>(proj_lb, lph, lpl, RR, CC);

    // ---- qkv: out bf16 hi/lo only ----
    gemm_la_kernel<<<M/32, 256>>>(x, qkv_la, a2, CC);
    convert_hilo_kernel<<<actN4/256, 256>>>(x, ah, al, actN4);
    convert_hilo_kernel<<<a2N4/256, 256>>>(a2, a2h, a2l, a2N4);
    mm_gemm_kernel<<<dim3(3*CC/128, M/128), 256, DSMB>>>(
        ah, al, a2h, a2l, wqh, wql, lqh, lql, nullptr, qkvh, qkvl,
        nullptr, nullptr, 0, 3*CC);

    // ---- attention (tensor-core) -> xo fp32 + ah/al bf16 ----
    attn_mma_kernel<<<dim3(SS/128, BB*HH), 256, ATT_SMEM>>>(
        qkvh, qkvl, mask, xo, ah, al);

    // ---- fc1 (gelu): out h fp32 + ah2/al2 ----
    gemm_la_kernel<<<M/32, 256>>>(xo, fc1_la, a2, CC);
    convert_hilo_kernel<<<a2N4/256, 256>>>(a2, a2h, a2l, a2N4);
    mm_gemm_kernel<<<dim3(CC/128, M/128), 256, DSMB>>>(
        ah, al, a2h, a2l, w1h, w1l, l1h, l1l, hbuf, ah2, al2, fc1_b, nullptr, 1, CC);

    // ---- fc2 (+ residual xo): out xo2 fp32 + ah/al ----
    gemm_la_kernel<<<M/32, 256>>>(hbuf, fc2_la, a2, CC);
    convert_hilo_kernel<<<a2N4/256, 256>>>(a2, a2h, a2l, a2N4);
    mm_gemm_kernel<<<dim3(CC/128, M/128), 256, DSMB>>>(
        ah2, al2, a2h, a2l, w2h, w2l, l2h, l2l, xo2, ah, al, fc2_b, xo, 0, CC);

    // ---- proj -> out ----
    gemm_la_kernel<<<M/32, 256>>>(xo2, proj_la, a2, CC);
    convert_hilo_kernel<<<a2N4/256, 256>>>(a2, a2h, a2l, a2N4);
    mm_gemm_kernel<<<dim3(CC/128, M/128), 256, DSMB>>>(
        ah, al, a2h, a2l, wph, wpl, lph, lpl, out, nullptr, nullptr,
        proj_b, nullptr, 0, CC);
}

// round 14
// speedup vs baseline: 3.2618x; 1.2208x over previous
#include <cuda_runtime.h>
#include <cuda_fp16.h>
#include <math.h>
#include <stdint.h>

#define BB 8
#define SS 512
#define CC 1024
#define HH 16
#define RR 32
#define MTOT (BB*SS)          // 4096
#define KK CC                 // GEMM K = 1024

// ---------------- fp32 scratch ----------------------------------------------
__device__ float g_xo [MTOT * CC];
__device__ float g_h  [MTOT * CC];
__device__ float g_xo2[MTOT * CC];
__device__ float g_a2 [MTOT * RR];

// ---------------- fp16 scratch ----------------------------------------------
__device__ __half g_qkvh[MTOT * 3 * CC], g_qkvl[MTOT * 3 * CC];
__device__ __half g_ah [MTOT * CC], g_al [MTOT * CC];   // act pair A
__device__ __half g_ah2[MTOT * CC], g_al2[MTOT * CC];   // act pair B
__device__ __half g_a2h[MTOT * RR], g_a2l[MTOT * RR];
__device__ __half g_wqkv[3*CC*CC];                      // weights: single fp16 [N,K]
__device__ __half g_wfc1[CC*CC];
__device__ __half g_wfc2[CC*CC];
__device__ __half g_wproj[CC*CC];
__device__ __half g_lbqkv[3*CC*RR];                     // [N,32]
__device__ __half g_lbfc1[CC*RR];
__device__ __half g_lbfc2[CC*RR];
__device__ __half g_lbproj[CC*RR];

// ---------------- helpers ----------------------------------------------------
__device__ __forceinline__ float gelu_exact(float x) {
    return 0.5f * x * (1.0f + erff(x * 0.70710678118654752440f));
}
__device__ __forceinline__ void mma_f16(float* c, const uint32_t* a,
                                        uint32_t b0, uint32_t b1) {
    asm volatile(
        "mma.sync.aligned.m16n8k16.row.col.f32.f16.f16.f32 "
        "{%0,%1,%2,%3}, {%4,%5,%6,%7}, {%8,%9}, {%0,%1,%2,%3};"
        : "+f"(c[0]), "+f"(c[1]), "+f"(c[2]), "+f"(c[3])
        : "r"(a[0]), "r"(a[1]), "r"(a[2]), "r"(a[3]), "r"(b0), "r"(b1));
}
__device__ __forceinline__ void ldsm4(uint32_t* r, uint32_t addr) {
    asm volatile("ldmatrix.sync.aligned.m8n8.x4.shared.b16 {%0,%1,%2,%3}, [%4];"
        : "=r"(r[0]), "=r"(r[1]), "=r"(r[2]), "=r"(r[3]) : "r"(addr));
}
__device__ __forceinline__ void ldsm4t(uint32_t* r, uint32_t addr) {
    asm volatile("ldmatrix.sync.aligned.m8n8.x4.trans.shared.b16 {%0,%1,%2,%3}, [%4];"
        : "=r"(r[0]), "=r"(r[1]), "=r"(r[2]), "=r"(r[3]) : "r"(addr));
}
#define CP_ASYNC16(dst_u32, src_ptr) \
    asm volatile("cp.async.cg.shared.global [%0], [%1], 16;" \
                 :: "r"(dst_u32), "l"(src_ptr))
#define CP_COMMIT() asm volatile("cp.async.commit_group;" ::: "memory")

__device__ __forceinline__ uint32_t packh(float x, float y) {
    __half2 t = __floats2half2_rn(x, y);
    return *(uint32_t*)&t;
}

// ---------------- HMMA fp16 (act hi/lo, weight single) GEMM ------------------
// C[M,N] = (Ah+Al)[M,K] @ B[N,K]^T + (A2h+A2l)[M,32] @ LB[N,32]^T
//          (+bias) (gelu?) (+res), optional fp16 hi/lo output (Ch/Cl)
#define TCSTRIDE 80            // bytes per smem row (32 fp16 + pad)
#define MATB 10240             // bytes per matrix tile (128 rows)
#define STAGEB (3*MATB)        // 30720: Ah, Al, B
#define DSMB (2*STAGEB)        // 61440

__global__ __launch_bounds__(256, 2) void mm_gemm_kernel(
    const __half* __restrict__ Ah,  const __half* __restrict__ Al,
    const __half* __restrict__ A2h, const __half* __restrict__ A2l,
    const __half* __restrict__ B,   const __half* __restrict__ LB,
    float* __restrict__ C, __half* __restrict__ Ch,
    __half* __restrict__ Cl, const float* __restrict__ bias,
    const float* __restrict__ res, int act, int N)
{
    extern __shared__ char dsm[];
    const int tid = threadIdx.x;
    const int row0 = blockIdx.y * 128;
    const int col0 = blockIdx.x * 128;
    const int w = tid >> 5, lane = tid & 31;
    const int gid = lane >> 2, t4 = lane & 3;
    const int wm = (w & 3) * 32, wn = (w >> 2) * 64;

    const uint32_t smem0 = (uint32_t)__cvta_generic_to_shared(dsm);

    const int a_r  = (lane & 15);
    const int a_ko = (lane >> 4) * 16;
    const int b_r  = (lane & 7) + ((lane >> 4) << 3);
    const int b_ko = ((lane >> 3) & 1) * 16;

    float acc[2][8][4];
#pragma unroll
    for (int i = 0; i < 2; i++)
#pragma unroll
        for (int j = 0; j < 8; j++)
#pragma unroll
            for (int r = 0; r < 4; r++) acc[i][j][r] = 0.f;

    auto load_stage = [&](int buf, int kc) {
        const uint32_t sb = smem0 + buf * STAGEB;
        const bool lora = (kc == 32);
        const int koff = lora ? 0 : kc * 32;
        const int strd = lora ? RR : KK;
        const __half* p0 = lora ? A2h : Ah;
        const __half* p1 = lora ? A2l : Al;
        const __half* p2 = lora ? LB : B;
#pragma unroll
        for (int t = 0; t < 6; t++) {
            const int idx = tid + t * 256;       // 0..1535
            const int m = idx >> 9;              // 0=Ah 1=Al 2=B
            const int r = (idx >> 2) & 127;
            const int q = idx & 3;
            const __half* base = (m == 0) ? p0 : (m == 1) ? p1 : p2;
            const int grow = ((m < 2) ? row0 : col0) + r;
            const __half* src = base + (size_t)grow * strd + koff + q * 8;
            const uint32_t dst = sb + m * MATB + r * TCSTRIDE + q * 16;
            CP_ASYNC16(dst, src);
        }
        CP_COMMIT();
    };

    auto compute = [&](int buf) {
        const uint32_t sb = smem0 + buf * STAGEB;
#pragma unroll
        for (int ks = 0; ks < 2; ks++) {
            const int kb = ks * 32;              // bytes
            uint32_t a[2][2][4];                 // [mtile][hi/lo][reg]
#pragma unroll
            for (int i = 0; i < 2; i++) {
                const uint32_t ra = (wm + i * 16 + a_r) * TCSTRIDE + kb + a_ko;
                ldsm4(a[i][0], sb + ra);
                ldsm4(a[i][1], sb + MATB + ra);
            }
#pragma unroll
            for (int jp = 0; jp < 4; jp++) {
                uint32_t bb[4];
                const uint32_t rb = (wn + jp * 16 + b_r) * TCSTRIDE + kb + b_ko;
                ldsm4(bb, sb + 2 * MATB + rb);
#pragma unroll
                for (int i = 0; i < 2; i++) {
                    mma_f16(acc[i][2*jp],   a[i][0], bb[0], bb[1]);
                    mma_f16(acc[i][2*jp],   a[i][1], bb[0], bb[1]);
                    mma_f16(acc[i][2*jp+1], a[i][0], bb[2], bb[3]);
                    mma_f16(acc[i][2*jp+1], a[i][1], bb[2], bb[3]);
                }
            }
        }
    };

    load_stage(0, 0);
    for (int kc = 0; kc < 33; kc++) {
        if (kc + 1 < 33) {
            load_stage((kc + 1) & 1, kc + 1);
            asm volatile("cp.async.wait_group 1;" ::: "memory");
        } else {
            asm volatile("cp.async.wait_group 0;" ::: "memory");
        }
        __syncthreads();
        compute(kc & 1);
        __syncthreads();
    }

#pragma unroll
    for (int i = 0; i < 2; i++) {
        const int r0 = row0 + wm + i * 16 + gid;
#pragma unroll
        for (int j = 0; j < 8; j++) {
            const int col = col0 + wn + j * 8 + t4 * 2;
            float v0 = acc[i][j][0], v1 = acc[i][j][1];
            float v2 = acc[i][j][2], v3 = acc[i][j][3];
            if (bias) {
                const float b0 = bias[col], b1 = bias[col + 1];
                v0 += b0; v1 += b1; v2 += b0; v3 += b1;
            }
            if (act) {
                v0 = gelu_exact(v0); v1 = gelu_exact(v1);
                v2 = gelu_exact(v2); v3 = gelu_exact(v3);
            }
            if (res) {
                const float* rp0 = res + (size_t)r0 * N + col;
                const float* rp1 = res + (size_t)(r0 + 8) * N + col;
                v0 += rp0[0]; v1 += rp0[1]; v2 += rp1[0]; v3 += rp1[1];
            }
            if (C) {
                *(float2*)(C + (size_t)r0 * N + col) = make_float2(v0, v1);
                *(float2*)(C + (size_t)(r0 + 8) * N + col) = make_float2(v2, v3);
            }
            if (Ch) {
                const __half h0 = __float2half_rn(v0);
                const __half h1 = __float2half_rn(v1);
                const __half h2 = __float2half_rn(v2);
                const __half h3 = __float2half_rn(v3);
                *(__half2*)(Ch + (size_t)r0 * N + col) = __halves2half2(h0, h1);
                *(__half2*)(Ch + (size_t)(r0 + 8) * N + col) = __halves2half2(h2, h3);
                *(__half2*)(Cl + (size_t)r0 * N + col) = __halves2half2(
                    __float2half_rn(v0 - __half2float(h0)),
                    __float2half_rn(v1 - __half2float(h1)));
                *(__half2*)(Cl + (size_t)(r0 + 8) * N + col) = __halves2half2(
                    __float2half_rn(v2 - __half2float(h2)),
                    __float2half_rn(v3 - __half2float(h3)));
            }
        }
    }
}

// ---------------- prep kernels ----------------------------------------------
// W[K,N] fp32 -> Wt [N,K] fp16 (single)
__global__ __launch_bounds__(256) void transpose_convert_kernel(
    const float* __restrict__ W, __half* __restrict__ Th, int K, int N)
{
    __shared__ float s[32][33];
    const int tx = threadIdx.x & 31, ty = threadIdx.x >> 5;
    const int n0 = blockIdx.x * 32, k0 = blockIdx.y * 32;
#pragma unroll
    for (int i = 0; i < 4; i++)
        s[ty + 8*i][tx] = W[(size_t)(k0 + ty + 8*i) * N + n0 + tx];
    __syncthreads();
#pragma unroll
    for (int i = 0; i < 4; i++) {
        const int n = ty + 8*i;
        Th[(size_t)(n0 + n) * K + k0 + tx] = __float2half_rn(s[tx][n]);
    }
}

// fp32 -> fp16 hi/lo
__global__ __launch_bounds__(256) void convert_hilo_kernel(
    const float* __restrict__ in, __half* __restrict__ oh,
    __half* __restrict__ ol, int n4)
{
    const int i = blockIdx.x * 256 + threadIdx.x;
    if (i >= n4) return;
    const float4 v = ((const float4*)in)[i];
    const __half hx = __float2half_rn(v.x);
    const __half hy = __float2half_rn(v.y);
    const __half hz = __float2half_rn(v.z);
    const __half hw = __float2half_rn(v.w);
    ((__half2*)oh)[2*i]   = __halves2half2(hx, hy);
    ((__half2*)oh)[2*i+1] = __halves2half2(hz, hw);
    ((__half2*)ol)[2*i]   = __halves2half2(
        __float2half_rn(v.x - __half2float(hx)),
        __float2half_rn(v.y - __half2float(hy)));
    ((__half2*)ol)[2*i+1] = __halves2half2(
        __float2half_rn(v.z - __half2float(hz)),
        __float2half_rn(v.w - __half2float(hw)));
}

// ---------------- LoRA A-projection ------------------------------------------
__global__ __launch_bounds__(256) void gemm_la_kernel(
    const float* __restrict__ A, const float* __restrict__ LA,
    float* __restrict__ A2, int K)
{
    __shared__ float sA[32 * 32];
    __shared__ float sLAt[32 * 36];
    const int tid = threadIdx.x;
    const int row0 = blockIdx.x * 32;
    const int col = tid & 31;
    const int rgrp = tid >> 5;

    float s[4] = {0.f, 0.f, 0.f, 0.f};

    for (int k0 = 0; k0 < K; k0 += 32) {
        __syncthreads();
        {
            const int r = tid >> 3, c = (tid & 7) * 4;
            *(float4*)&sA[r * 32 + c] =
                *(const float4*)(A + (size_t)(row0 + r) * K + k0 + c);
        }
#pragma unroll
        for (int t = 0; t < 4; t++) {
            const int idx = tid + t * 256;
            const int kk = idx >> 5, c = idx & 31;
            sLAt[c * 36 + kk] = LA[(size_t)(k0 + kk) * 32 + c];
        }
        __syncthreads();
#pragma unroll
        for (int kk = 0; kk < 32; kk += 4) {
            const float4 la = *(const float4*)&sLAt[col * 36 + kk];
#pragma unroll
            for (int rr = 0; rr < 4; rr++) {
                const float4 a = *(const float4*)&sA[(rgrp + rr * 8) * 32 + kk];
                s[rr] += a.x * la.x + a.y * la.y + a.z * la.z + a.w * la.w;
            }
        }
    }
#pragma unroll
    for (int rr = 0; rr < 4; rr++)
        A2[(size_t)(row0 + rgrp + rr * 8) * 32 + col] = s[rr];
}

// ---------------- tensor-core flash attention (fp16 hi/lo, 3-MMA) ------------
#define ATSTR 144              // smem row stride bytes (64 fp16 + pad)
#define ATT_QB (128*ATSTR)     // 18432
#define ATT_T  (64*ATSTR)      // 9216
#define ATT_BUF (4*ATT_T)      // 36864
#define ATT_SMEM (2*ATT_QB + 2*ATT_BUF + 512)

__global__ __launch_bounds__(256, 1) void attn_mma_kernel(
    const __half* __restrict__ qkvh,
    const __half* __restrict__ qkvl,
    const int* __restrict__ mask,
    float* __restrict__ xo, __half* __restrict__ xoh,
    __half* __restrict__ xol)
{
    extern __shared__ char dsm[];
    const int tid = threadIdx.x;
    const int w = tid >> 5, lane = tid & 31;
    const int gid = lane >> 2, t4 = lane & 3;
    const int bh = blockIdx.y, b = bh >> 4, h = bh & 15;
    const int qblk = blockIdx.x * 128;

    const uint32_t s0 = (uint32_t)__cvta_generic_to_shared(dsm);
    const uint32_t sQ = s0;
    const uint32_t sKV = s0 + 2 * ATT_QB;
    const uint32_t sMk = sKV + 2 * ATT_BUF;

    const int a_r = lane & 15, a_ko = (lane >> 4) * 16;
    const int b_r = (lane & 7) + ((lane >> 4) << 3);
    const int b_ko = ((lane >> 3) & 1) * 16;

#pragma unroll
    for (int t = 0; t < 8; t++) {
        const int idx = tid + t * 256;
        const int m = idx >> 10;                 // 0=Qh 1=Ql
        const int r = (idx >> 3) & 127;
        const int q = idx & 7;
        const __half* src = (m ? qkvl : qkvh)
            + (size_t)(b * SS + qblk + r) * 3072 + h * 64 + q * 8;
        CP_ASYNC16(sQ + m * ATT_QB + r * ATSTR + q * 16, src);
    }
    auto load_tile = [&](int kt, int buf) {
#pragma unroll
        for (int t = 0; t < 8; t++) {
            const int idx = tid + t * 256;
            const int m = idx >> 9;              // 0=Kh 1=Kl 2=Vh 3=Vl
            const int r = (idx >> 3) & 63;
            const int q = idx & 7;
            const int colb = ((m < 2) ? 1024 : 2048) + h * 64;
            const __half* src = ((m & 1) ? qkvl : qkvh)
                + (size_t)(b * SS + kt * 64 + r) * 3072 + colb + q * 8;
            CP_ASYNC16(sKV + buf * ATT_BUF + m * ATT_T + r * ATSTR + q * 16, src);
        }
        if (tid < 16)
            CP_ASYNC16(sMk + buf * 256 + tid * 16,
                       mask + (size_t)b * (3 * SS) + kt * 64 + tid * 4);
        CP_COMMIT();
    };
    load_tile(0, 0);
    CP_COMMIT();

    float o[8][4];
#pragma unroll
    for (int j = 0; j < 8; j++)
#pragma unroll
        for (int r = 0; r < 4; r++) o[j][r] = 0.f;
    float mr0 = -INFINITY, mr1 = -INFINITY, l0 = 0.f, l1 = 0.f;

    for (int kt = 0; kt < 8; kt++) {
        const int buf = kt & 1;
        if (kt < 7) {
            load_tile(kt + 1, buf ^ 1);
            asm volatile("cp.async.wait_group 1;" ::: "memory");
        } else {
            asm volatile("cp.async.wait_group 0;" ::: "memory");
        }
        __syncthreads();

        const uint32_t kB = sKV + buf * ATT_BUF;
        const int* msk = (const int*)(dsm + (2 * ATT_QB + 2 * ATT_BUF) + buf * 256);

        float s[8][4];
#pragma unroll
        for (int j = 0; j < 8; j++)
#pragma unroll
            for (int r = 0; r < 4; r++) s[j][r] = 0.f;
#pragma unroll
        for (int ks = 0; ks < 4; ks++) {
            uint32_t qh[4], ql[4];
            const uint32_t qa = sQ + (w * 16 + a_r) * ATSTR + ks * 32 + a_ko;
            ldsm4(qh, qa);
            ldsm4(ql, qa + ATT_QB);
#pragma unroll
            for (int jp = 0; jp < 4; jp++) {
                uint32_t bh4[4], bl4[4];
                const uint32_t ba = kB + (jp * 16 + b_r) * ATSTR + ks * 32 + b_ko;
                ldsm4(bh4, ba);
                ldsm4(bl4, ba + ATT_T);
                mma_f16(s[2*jp],   qh, bh4[0], bh4[1]);
                mma_f16(s[2*jp],   qh, bl4[0], bl4[1]);
                mma_f16(s[2*jp],   ql, bh4[0], bh4[1]);
                mma_f16(s[2*jp+1], qh, bh4[2], bh4[3]);
                mma_f16(s[2*jp+1], qh, bl4[2], bl4[3]);
                mma_f16(s[2*jp+1], ql, bh4[2], bh4[3]);
            }
        }

        float tm0 = -INFINITY, tm1 = -INFINITY;
#pragma unroll
        for (int j = 0; j < 8; j++) {
            const int c0 = 8 * j + 2 * t4;
            const bool v0 = msk[c0] != 0, v1 = msk[c0 + 1] != 0;
            s[j][0] = v0 ? s[j][0] * 0.125f : -INFINITY;
            s[j][1] = v1 ? s[j][1] * 0.125f : -INFINITY;
            s[j][2] = v0 ? s[j][2] * 0.125f : -INFINITY;
            s[j][3] = v1 ? s[j][3] * 0.125f : -INFINITY;
            tm0 = fmaxf(tm0, fmaxf(s[j][0], s[j][1]));
            tm1 = fmaxf(tm1, fmaxf(s[j][2], s[j][3]));
        }
        tm0 = fmaxf(tm0, __shfl_xor_sync(0xffffffffu, tm0, 1));
        tm0 = fmaxf(tm0, __shfl_xor_sync(0xffffffffu, tm0, 2));
        tm1 = fmaxf(tm1, __shfl_xor_sync(0xffffffffu, tm1, 1));
        tm1 = fmaxf(tm1, __shfl_xor_sync(0xffffffffu, tm1, 2));
        const float nm0 = fmaxf(mr0, tm0), nm1 = fmaxf(mr1, tm1);
        const float nb0 = (nm0 == -INFINITY) ? 0.f : nm0;
        const float nb1 = (nm1 == -INFINITY) ? 0.f : nm1;
        const float cr0 = __expf(mr0 - nb0), cr1 = __expf(mr1 - nb1);
        float sum0 = 0.f, sum1 = 0.f;
#pragma unroll
        for (int j = 0; j < 8; j++) {
            s[j][0] = __expf(s[j][0] - nb0);
            s[j][1] = __expf(s[j][1] - nb0);
            s[j][2] = __expf(s[j][2] - nb1);
            s[j][3] = __expf(s[j][3] - nb1);
            sum0 += s[j][0] + s[j][1];
            sum1 += s[j][2] + s[j][3];
            o[j][0] *= cr0; o[j][1] *= cr0;
            o[j][2] *= cr1; o[j][3] *= cr1;
        }
        sum0 += __shfl_xor_sync(0xffffffffu, sum0, 1);
        sum0 += __shfl_xor_sync(0xffffffffu, sum0, 2);
        sum1 += __shfl_xor_sync(0xffffffffu, sum1, 1);
        sum1 += __shfl_xor_sync(0xffffffffu, sum1, 2);
        l0 = l0 * cr0 + sum0;
        l1 = l1 * cr1 + sum1;
        mr0 = nm0; mr1 = nm1;

#pragma unroll
        for (int kt2 = 0; kt2 < 4; kt2++) {
            uint32_t pah[4], pal[4];
            {
                const float* pj0 = s[2 * kt2];
                const float* pj1 = s[2 * kt2 + 1];
                pah[0] = packh(pj0[0], pj0[1]);
                pah[1] = packh(pj0[2], pj0[3]);
                pah[2] = packh(pj1[0], pj1[1]);
                pah[3] = packh(pj1[2], pj1[3]);
                const __half2* h0 = (const __half2*)&pah[0];
                pal[0] = packh(pj0[0] - __half2float(h0->x),
                               pj0[1] - __half2float(h0->y));
                const __half2* h1 = (const __half2*)&pah[1];
                pal[1] = packh(pj0[2] - __half2float(h1->x),
                               pj0[3] - __half2float(h1->y));
                const __half2* h2 = (const __half2*)&pah[2];
                pal[2] = packh(pj1[0] - __half2float(h2->x),
                               pj1[1] - __half2float(h2->y));
                const __half2* h3 = (const __half2*)&pah[3];
                pal[3] = packh(pj1[2] - __half2float(h3->x),
                               pj1[3] - __half2float(h3->y));
            }
#pragma unroll
            for (int jp = 0; jp < 4; jp++) {
                uint32_t vh4[4], vl4[4];
                const uint32_t va = kB + 2 * ATT_T
                    + (kt2 * 16 + a_r) * ATSTR + jp * 32 + a_ko;
                ldsm4t(vh4, va);
                ldsm4t(vl4, va + ATT_T);
                mma_f16(o[2*jp],   pah, vh4[0], vh4[1]);
                mma_f16(o[2*jp],   pah, vl4[0], vl4[1]);
                mma_f16(o[2*jp],   pal, vh4[0], vh4[1]);
                mma_f16(o[2*jp+1], pah, vh4[2], vh4[3]);
                mma_f16(o[2*jp+1], pah, vl4[2], vl4[3]);
                mma_f16(o[2*jp+1], pal, vh4[2], vh4[3]);
            }
        }
        __syncthreads();
    }

    const float inv0 = (l0 > 0.f) ? (1.f / l0) : 0.f;
    const float inv1 = (l1 > 0.f) ? (1.f / l1) : 0.f;
    const size_t ob0 = (size_t)(b * SS + qblk + w * 16 + gid) * CC + h * 64;
    const size_t ob1 = ob0 + (size_t)8 * CC;
#pragma unroll
    for (int j = 0; j < 8; j++) {
        const int col = 8 * j + 2 * t4;
        const float v0 = o[j][0] * inv0, v1 = o[j][1] * inv0;
        const float v2 = o[j][2] * inv1, v3 = o[j][3] * inv1;
        *(float2*)(xo + ob0 + col) = make_float2(v0, v1);
        *(float2*)(xo + ob1 + col) = make_float2(v2, v3);
        const __half h0 = __float2half_rn(v0);
        const __half h1 = __float2half_rn(v1);
        const __half h2 = __float2half_rn(v2);
        const __half h3 = __float2half_rn(v3);
        *(__half2*)(xoh + ob0 + col) = __halves2half2(h0, h1);
        *(__half2*)(xoh + ob1 + col) = __halves2half2(h2, h3);
        *(__half2*)(xol + ob0 + col) = __halves2half2(
            __float2half_rn(v0 - __half2float(h0)),
            __float2half_rn(v1 - __half2float(h1)));
        *(__half2*)(xol + ob1 + col) = __halves2half2(
            __float2half_rn(v2 - __half2float(h2)),
            __float2half_rn(v3 - __half2float(h3)));
    }
}

// ---------------- launch -----------------------------------------------------
extern "C" void kernel_launch(void* const* d_in, const int* in_sizes, int n_in,
                              void* d_out, int out_size)
{
    const float* x        = (const float*)d_in[0];
    const int*   mask     = (const int*)d_in[1];
    const float* qkv_w    = (const float*)d_in[2];
    const float* qkv_la   = (const float*)d_in[3];
    const float* qkv_lb   = (const float*)d_in[4];
    const float* proj_w   = (const float*)d_in[5];
    const float* proj_b   = (const float*)d_in[6];
    const float* proj_la  = (const float*)d_in[7];
    const float* proj_lb  = (const float*)d_in[8];
    const float* fc1_w    = (const float*)d_in[9];
    const float* fc1_b    = (const float*)d_in[10];
    const float* fc1_la   = (const float*)d_in[11];
    const float* fc1_lb   = (const float*)d_in[12];
    const float* fc2_w    = (const float*)d_in[13];
    const float* fc2_b    = (const float*)d_in[14];
    const float* fc2_la   = (const float*)d_in[15];
    const float* fc2_lb   = (const float*)d_in[16];
    float* out = (float*)d_out;

    float *xo, *hbuf, *xo2, *a2;
    cudaGetSymbolAddress((void**)&xo,  g_xo);
    cudaGetSymbolAddress((void**)&hbuf, g_h);
    cudaGetSymbolAddress((void**)&xo2, g_xo2);
    cudaGetSymbolAddress((void**)&a2,  g_a2);

    __half *qkvh,*qkvl,*ah,*al,*ah2,*al2,*a2h,*a2l;
    __half *wq,*w1,*w2,*wp,*lq,*l1,*l2,*lp;
    cudaGetSymbolAddress((void**)&qkvh, g_qkvh); cudaGetSymbolAddress((void**)&qkvl, g_qkvl);
    cudaGetSymbolAddress((void**)&ah,  g_ah);   cudaGetSymbolAddress((void**)&al,  g_al);
    cudaGetSymbolAddress((void**)&ah2, g_ah2);  cudaGetSymbolAddress((void**)&al2, g_al2);
    cudaGetSymbolAddress((void**)&a2h, g_a2h);  cudaGetSymbolAddress((void**)&a2l, g_a2l);
    cudaGetSymbolAddress((void**)&wq, g_wqkv);
    cudaGetSymbolAddress((void**)&w1, g_wfc1);
    cudaGetSymbolAddress((void**)&w2, g_wfc2);
    cudaGetSymbolAddress((void**)&wp, g_wproj);
    cudaGetSymbolAddress((void**)&lq, g_lbqkv);
    cudaGetSymbolAddress((void**)&l1, g_lbfc1);
    cudaGetSymbolAddress((void**)&l2, g_lbfc2);
    cudaGetSymbolAddress((void**)&lp, g_lbproj);

    cudaFuncSetAttribute(mm_gemm_kernel,
                         cudaFuncAttributeMaxDynamicSharedMemorySize, DSMB);
    cudaFuncSetAttribute(attn_mma_kernel,
                         cudaFuncAttributeMaxDynamicSharedMemorySize, ATT_SMEM);

    const int M = MTOT;
    const int actN4 = M * CC / 4;
    const int a2N4  = M * RR / 4;

    // ---- weight prep (transpose + fp16 convert) ----
    transpose_convert_kernel<<<dim3(3*CC/32, CC/32), 256>>>(qkv_w, wq, CC, 3*CC);
    transpose_convert_kernel<<<dim3(CC/32,  CC/32), 256>>>(fc1_w, w1, CC, CC);
    transpose_convert_kernel<<<dim3(CC/32,  CC/32), 256>>>(fc2_w, w2, CC, CC);
    transpose_convert_kernel<<<dim3(CC/32,  CC/32), 256>>>(proj_w, wp, CC, CC);
    transpose_convert_kernel<<<dim3(3*CC/32, 1), 256>>>(qkv_lb, lq, RR, 3*CC);
    transpose_convert_kernel<<<dim3(CC/32, 1), 256>>>(fc1_lb, l1, RR, CC);
    transpose_convert_kernel<<<dim3(CC/32, 1), 256>>>(fc2_lb, l2, RR, CC);
    transpose_convert_kernel<<<dim3(CC/32, 1), 256>>>(proj_lb, lp, RR, CC);

    // ---- qkv: out fp16 hi/lo only ----
    gemm_la_kernel<<<M/32, 256>>>(x, qkv_la, a2, CC);
    convert_hilo_kernel<<<actN4/256, 256>>>(x, ah, al, actN4);
    convert_hilo_kernel<<<a2N4/256, 256>>>(a2, a2h, a2l, a2N4);
    mm_gemm_kernel<<<dim3(3*CC/128, M/128), 256, DSMB>>>(
        ah, al, a2h, a2l, wq, lq, nullptr, qkvh, qkvl,
        nullptr, nullptr, 0, 3*CC);

    // ---- attention -> xo fp32 + ah/al fp16 ----
    attn_mma_kernel<<<dim3(SS/128, BB*HH), 256, ATT_SMEM>>>(
        qkvh, qkvl, mask, xo, ah, al);

    // ---- fc1 (gelu): out h fp32 + ah2/al2 ----
    gemm_la_kernel<<<M/32, 256>>>(xo, fc1_la, a2, CC);
    convert_hilo_kernel<<<a2N4/256, 256>>>(a2, a2h, a2l, a2N4);
    mm_gemm_kernel<<<dim3(CC/128, M/128), 256, DSMB>>>(
        ah, al, a2h, a2l, w1, l1, hbuf, ah2, al2, fc1_b, nullptr, 1, CC);

    // ---- fc2 (+ residual xo): out xo2 fp32 + ah/al ----
    gemm_la_kernel<<<M/32, 256>>>(hbuf, fc2_la, a2, CC);
    convert_hilo_kernel<<<a2N4/256, 256>>>(a2, a2h, a2l, a2N4);
    mm_gemm_kernel<<<dim3(CC/128, M/128), 256, DSMB>>>(
        ah2, al2, a2h, a2l, w2, l2, xo2, ah, al, fc2_b, xo, 0, CC);

    // ---- proj -> out ----
    gemm_la_kernel<<<M/32, 256>>>(xo2, proj_la, a2, CC);
    convert_hilo_kernel<<<a2N4/256, 256>>>(a2, a2h, a2l, a2N4);
    mm_gemm_kernel<<<dim3(CC/128, M/128), 256, DSMB>>>(
        ah, al, a2h, a2l, wp, lp, out, nullptr, nullptr,
        proj_b, nullptr, 0, CC);
}

// round 16
// speedup vs baseline: 3.5765x; 1.0965x over previous
#include <cuda_runtime.h>
#include <cuda_fp16.h>
#include <math.h>
#include <stdint.h>

#define BB 8
#define SS 512
#define CC 1024
#define HH 16
#define RR 32
#define MTOT (BB*SS)          // 4096
#define KK CC                 // GEMM K = 1024

// ---------------- fp16 scratch ----------------------------------------------
__device__ __half g_qkvh[MTOT * 3 * CC], g_qkvl[MTOT * 3 * CC];
__device__ __half g_ah [MTOT * CC], g_al [MTOT * CC];   // act pair A
__device__ __half g_ah2[MTOT * CC], g_al2[MTOT * CC];   // act pair B
__device__ __half g_a2h[MTOT * RR], g_a2l[MTOT * RR];
__device__ __half g_wqkv[3*CC*CC];                      // weights fp16 [N,K]
__device__ __half g_wfc1[CC*CC];
__device__ __half g_wfc2[CC*CC];
__device__ __half g_wproj[CC*CC];
__device__ __half g_lbqkv[3*CC*RR];                     // [N,32]
__device__ __half g_lbfc1[CC*RR];
__device__ __half g_lbfc2[CC*RR];
__device__ __half g_lbproj[CC*RR];

// ---------------- helpers ----------------------------------------------------
__device__ __forceinline__ float gelu_exact(float x) {
    return 0.5f * x * (1.0f + erff(x * 0.70710678118654752440f));
}
__device__ __forceinline__ void mma_f16(float* c, const uint32_t* a,
                                        uint32_t b0, uint32_t b1) {
    asm volatile(
        "mma.sync.aligned.m16n8k16.row.col.f32.f16.f16.f32 "
        "{%0,%1,%2,%3}, {%4,%5,%6,%7}, {%8,%9}, {%0,%1,%2,%3};"
        : "+f"(c[0]), "+f"(c[1]), "+f"(c[2]), "+f"(c[3])
        : "r"(a[0]), "r"(a[1]), "r"(a[2]), "r"(a[3]), "r"(b0), "r"(b1));
}
__device__ __forceinline__ void ldsm4(uint32_t* r, uint32_t addr) {
    asm volatile("ldmatrix.sync.aligned.m8n8.x4.shared.b16 {%0,%1,%2,%3}, [%4];"
        : "=r"(r[0]), "=r"(r[1]), "=r"(r[2]), "=r"(r[3]) : "r"(addr));
}
__device__ __forceinline__ void ldsm4t(uint32_t* r, uint32_t addr) {
    asm volatile("ldmatrix.sync.aligned.m8n8.x4.trans.shared.b16 {%0,%1,%2,%3}, [%4];"
        : "=r"(r[0]), "=r"(r[1]), "=r"(r[2]), "=r"(r[3]) : "r"(addr));
}
#define CP_ASYNC16(dst_u32, src_ptr) \
    asm volatile("cp.async.cg.shared.global [%0], [%1], 16;" \
                 :: "r"(dst_u32), "l"(src_ptr))
#define CP_COMMIT() asm volatile("cp.async.commit_group;" ::: "memory")

__device__ __forceinline__ uint32_t packh(float x, float y) {
    __half2 t = __floats2half2_rn(x, y);
    return *(uint32_t*)&t;
}

// ---------------- HMMA fp16 GEMM (3-stage pipeline) --------------------------
// C/Ch[M,N] = (Ah+Al)[M,K] @ B[N,K]^T + (A2h+A2l)[M,32] @ LB[N,32]^T
//             (+bias) (gelu?) (+res from fp16 hi/lo)
#define TCSTRIDE 80            // bytes per smem row (32 fp16 + pad)
#define MATB 10240             // bytes per matrix tile (128 rows)
#define STAGEB (3*MATB)        // 30720: Ah, Al, B
#define DSMB (3*STAGEB)        // 92160 (3 stages)

__global__ __launch_bounds__(256, 2) void mm_gemm_kernel(
    const __half* __restrict__ Ah,  const __half* __restrict__ Al,
    const __half* __restrict__ A2h, const __half* __restrict__ A2l,
    const __half* __restrict__ B,   const __half* __restrict__ LB,
    float* __restrict__ C, __half* __restrict__ Ch,
    __half* __restrict__ Cl, const float* __restrict__ bias,
    const __half* __restrict__ resh, const __half* __restrict__ resl,
    int act, int N)
{
    extern __shared__ char dsm[];
    const int tid = threadIdx.x;
    const int row0 = blockIdx.y * 128;
    const int col0 = blockIdx.x * 128;
    const int w = tid >> 5, lane = tid & 31;
    const int gid = lane >> 2, t4 = lane & 3;
    const int wm = (w & 3) * 32, wn = (w >> 2) * 64;

    const uint32_t smem0 = (uint32_t)__cvta_generic_to_shared(dsm);

    const int a_r  = (lane & 15);
    const int a_ko = (lane >> 4) * 16;
    const int b_r  = (lane & 7) + ((lane >> 4) << 3);
    const int b_ko = ((lane >> 3) & 1) * 16;

    float acc[2][8][4];
#pragma unroll
    for (int i = 0; i < 2; i++)
#pragma unroll
        for (int j = 0; j < 8; j++)
#pragma unroll
            for (int r = 0; r < 4; r++) acc[i][j][r] = 0.f;

    auto load_stage = [&](int buf, int kc) {
        const uint32_t sb = smem0 + buf * STAGEB;
        const bool lora = (kc == 32);
        const int koff = lora ? 0 : kc * 32;
        const int strd = lora ? RR : KK;
        const __half* p0 = lora ? A2h : Ah;
        const __half* p1 = lora ? A2l : Al;
        const __half* p2 = lora ? LB : B;
#pragma unroll
        for (int t = 0; t < 6; t++) {
            const int idx = tid + t * 256;       // 0..1535
            const int m = idx >> 9;              // 0=Ah 1=Al 2=B
            const int r = (idx >> 2) & 127;
            const int q = idx & 3;
            const __half* base = (m == 0) ? p0 : (m == 1) ? p1 : p2;
            const int grow = ((m < 2) ? row0 : col0) + r;
            const __half* src = base + (size_t)grow * strd + koff + q * 8;
            const uint32_t dst = sb + m * MATB + r * TCSTRIDE + q * 16;
            CP_ASYNC16(dst, src);
        }
        CP_COMMIT();
    };

    auto compute = [&](int buf) {
        const uint32_t sb = smem0 + buf * STAGEB;
#pragma unroll
        for (int ks = 0; ks < 2; ks++) {
            const int kb = ks * 32;              // bytes
            uint32_t a[2][2][4];                 // [mtile][hi/lo][reg]
#pragma unroll
            for (int i = 0; i < 2; i++) {
                const uint32_t ra = (wm + i * 16 + a_r) * TCSTRIDE + kb + a_ko;
                ldsm4(a[i][0], sb + ra);
                ldsm4(a[i][1], sb + MATB + ra);
            }
#pragma unroll
            for (int jp = 0; jp < 4; jp++) {
                uint32_t bb[4];
                const uint32_t rb = (wn + jp * 16 + b_r) * TCSTRIDE + kb + b_ko;
                ldsm4(bb, sb + 2 * MATB + rb);
#pragma unroll
                for (int i = 0; i < 2; i++) {
                    mma_f16(acc[i][2*jp],   a[i][0], bb[0], bb[1]);
                    mma_f16(acc[i][2*jp],   a[i][1], bb[0], bb[1]);
                    mma_f16(acc[i][2*jp+1], a[i][0], bb[2], bb[3]);
                    mma_f16(acc[i][2*jp+1], a[i][1], bb[2], bb[3]);
                }
            }
        }
    };

    // 3-stage pipeline, one barrier per chunk
    load_stage(0, 0);
    load_stage(1, 1);
    for (int kc = 0; kc < 33; kc++) {
        if (kc < 32) {
            asm volatile("cp.async.wait_group 1;" ::: "memory");
        } else {
            asm volatile("cp.async.wait_group 0;" ::: "memory");
        }
        __syncthreads();
        if (kc + 2 < 33) load_stage((kc + 2) % 3, kc + 2);
        compute(kc % 3);
    }

#pragma unroll
    for (int i = 0; i < 2; i++) {
        const int r0 = row0 + wm + i * 16 + gid;
#pragma unroll
        for (int j = 0; j < 8; j++) {
            const int col = col0 + wn + j * 8 + t4 * 2;
            float v0 = acc[i][j][0], v1 = acc[i][j][1];
            float v2 = acc[i][j][2], v3 = acc[i][j][3];
            if (bias) {
                const float b0 = bias[col], b1 = bias[col + 1];
                v0 += b0; v1 += b1; v2 += b0; v3 += b1;
            }
            if (act) {
                v0 = gelu_exact(v0); v1 = gelu_exact(v1);
                v2 = gelu_exact(v2); v3 = gelu_exact(v3);
            }
            if (resh) {
                const __half2 rh0 = *(const __half2*)(resh + (size_t)r0 * N + col);
                const __half2 rl0 = *(const __half2*)(resl + (size_t)r0 * N + col);
                const __half2 rh1 = *(const __half2*)(resh + (size_t)(r0 + 8) * N + col);
                const __half2 rl1 = *(const __half2*)(resl + (size_t)(r0 + 8) * N + col);
                v0 += __half2float(rh0.x) + __half2float(rl0.x);
                v1 += __half2float(rh0.y) + __half2float(rl0.y);
                v2 += __half2float(rh1.x) + __half2float(rl1.x);
                v3 += __half2float(rh1.y) + __half2float(rl1.y);
            }
            if (C) {
                *(float2*)(C + (size_t)r0 * N + col) = make_float2(v0, v1);
                *(float2*)(C + (size_t)(r0 + 8) * N + col) = make_float2(v2, v3);
            }
            if (Ch) {
                const __half h0 = __float2half_rn(v0);
                const __half h1 = __float2half_rn(v1);
                const __half h2 = __float2half_rn(v2);
                const __half h3 = __float2half_rn(v3);
                *(__half2*)(Ch + (size_t)r0 * N + col) = __halves2half2(h0, h1);
                *(__half2*)(Ch + (size_t)(r0 + 8) * N + col) = __halves2half2(h2, h3);
                *(__half2*)(Cl + (size_t)r0 * N + col) = __halves2half2(
                    __float2half_rn(v0 - __half2float(h0)),
                    __float2half_rn(v1 - __half2float(h1)));
                *(__half2*)(Cl + (size_t)(r0 + 8) * N + col) = __halves2half2(
                    __float2half_rn(v2 - __half2float(h2)),
                    __float2half_rn(v3 - __half2float(h3)));
            }
        }
    }
}

// ---------------- prep kernels ----------------------------------------------
__global__ __launch_bounds__(256) void transpose_convert_kernel(
    const float* __restrict__ W, __half* __restrict__ Th, int K, int N)
{
    __shared__ float s[32][33];
    const int tx = threadIdx.x & 31, ty = threadIdx.x >> 5;
    const int n0 = blockIdx.x * 32, k0 = blockIdx.y * 32;
#pragma unroll
    for (int i = 0; i < 4; i++)
        s[ty + 8*i][tx] = W[(size_t)(k0 + ty + 8*i) * N + n0 + tx];
    __syncthreads();
#pragma unroll
    for (int i = 0; i < 4; i++) {
        const int n = ty + 8*i;
        Th[(size_t)(n0 + n) * K + k0 + tx] = __float2half_rn(s[tx][n]);
    }
}

__global__ __launch_bounds__(256) void convert_hilo_kernel(
    const float* __restrict__ in, __half* __restrict__ oh,
    __half* __restrict__ ol, int n4)
{
    const int i = blockIdx.x * 256 + threadIdx.x;
    if (i >= n4) return;
    const float4 v = ((const float4*)in)[i];
    const __half hx = __float2half_rn(v.x);
    const __half hy = __float2half_rn(v.y);
    const __half hz = __float2half_rn(v.z);
    const __half hw = __float2half_rn(v.w);
    ((__half2*)oh)[2*i]   = __halves2half2(hx, hy);
    ((__half2*)oh)[2*i+1] = __halves2half2(hz, hw);
    ((__half2*)ol)[2*i]   = __halves2half2(
        __float2half_rn(v.x - __half2float(hx)),
        __float2half_rn(v.y - __half2float(hy)));
    ((__half2*)ol)[2*i+1] = __halves2half2(
        __float2half_rn(v.z - __half2float(hz)),
        __float2half_rn(v.w - __half2float(hw)));
}

// ---------------- LoRA A-projection (fp16 A-hi in, fp16 hi/lo out) ----------
__global__ __launch_bounds__(256) void gemm_la_h_kernel(
    const __half* __restrict__ A, const float* __restrict__ LA,
    __half* __restrict__ A2h, __half* __restrict__ A2l, int K)
{
    __shared__ float sA[32 * 32];
    __shared__ float sLAt[32 * 36];
    const int tid = threadIdx.x;
    const int row0 = blockIdx.x * 32;
    const int col = tid & 31;
    const int rgrp = tid >> 5;

    float s[4] = {0.f, 0.f, 0.f, 0.f};

    for (int k0 = 0; k0 < K; k0 += 32) {
        __syncthreads();
        {
            const int r = tid >> 3, c = (tid & 7) * 4;
            const uint2 v = *(const uint2*)(A + (size_t)(row0 + r) * K + k0 + c);
            const __half2 h01 = *(const __half2*)&v.x;
            const __half2 h23 = *(const __half2*)&v.y;
            sA[r * 32 + c + 0] = __half2float(h01.x);
            sA[r * 32 + c + 1] = __half2float(h01.y);
            sA[r * 32 + c + 2] = __half2float(h23.x);
            sA[r * 32 + c + 3] = __half2float(h23.y);
        }
#pragma unroll
        for (int t = 0; t < 4; t++) {
            const int idx = tid + t * 256;
            const int kk = idx >> 5, c = idx & 31;
            sLAt[c * 36 + kk] = LA[(size_t)(k0 + kk) * 32 + c];
        }
        __syncthreads();
#pragma unroll
        for (int kk = 0; kk < 32; kk += 4) {
            const float4 la = *(const float4*)&sLAt[col * 36 + kk];
#pragma unroll
            for (int rr = 0; rr < 4; rr++) {
                const float4 a = *(const float4*)&sA[(rgrp + rr * 8) * 32 + kk];
                s[rr] += a.x * la.x + a.y * la.y + a.z * la.z + a.w * la.w;
            }
        }
    }
#pragma unroll
    for (int rr = 0; rr < 4; rr++) {
        const float v = s[rr];
        const __half hh = __float2half_rn(v);
        const size_t o = (size_t)(row0 + rgrp + rr * 8) * 32 + col;
        A2h[o] = hh;
        A2l[o] = __float2half_rn(v - __half2float(hh));
    }
}

// ---------------- tensor-core flash attention --------------------------------
// QK: Qh*Kh (1 MMA); PV: Ph*(Vh+Vl) (2 MMAs). Output fp16 hi/lo only.
#define ATSTR 144              // smem row stride bytes
#define ATT_QB (128*ATSTR)     // 18432 (Qh only)
#define ATT_T  (64*ATSTR)      // 9216
#define ATT_BUF3 (3*ATT_T)     // Kh, Vh, Vl = 27648
#define ATT_SMEM (ATT_QB + 2*ATT_BUF3 + 512)

__global__ __launch_bounds__(256, 1) void attn_mma_kernel(
    const __half* __restrict__ qkvh,
    const __half* __restrict__ qkvl,
    const int* __restrict__ mask,
    __half* __restrict__ xoh, __half* __restrict__ xol)
{
    extern __shared__ char dsm[];
    const int tid = threadIdx.x;
    const int w = tid >> 5, lane = tid & 31;
    const int gid = lane >> 2, t4 = lane & 3;
    const int bh = blockIdx.y, b = bh >> 4, h = bh & 15;
    const int qblk = blockIdx.x * 128;

    const uint32_t s0 = (uint32_t)__cvta_generic_to_shared(dsm);
    const uint32_t sQ = s0;
    const uint32_t sKV = s0 + ATT_QB;
    const uint32_t sMk = sKV + 2 * ATT_BUF3;

    const int a_r = lane & 15, a_ko = (lane >> 4) * 16;
    const int b_r = (lane & 7) + ((lane >> 4) << 3);
    const int b_ko = ((lane >> 3) & 1) * 16;

    // Q hi only
#pragma unroll
    for (int t = 0; t < 4; t++) {
        const int idx = tid + t * 256;           // 0..1023
        const int r = idx >> 3;
        const int q = idx & 7;
        const __half* src = qkvh
            + (size_t)(b * SS + qblk + r) * 3072 + h * 64 + q * 8;
        CP_ASYNC16(sQ + r * ATSTR + q * 16, src);
    }
    auto load_tile = [&](int kt, int buf) {
#pragma unroll
        for (int t = 0; t < 6; t++) {
            const int idx = tid + t * 256;       // 0..1535
            const int m = idx >> 9;              // 0=Kh 1=Vh 2=Vl
            const int r = (idx >> 3) & 63;
            const int q = idx & 7;
            const int colb = ((m == 0) ? 1024 : 2048) + h * 64;
            const __half* src = ((m == 2) ? qkvl : qkvh)
                + (size_t)(b * SS + kt * 64 + r) * 3072 + colb + q * 8;
            CP_ASYNC16(sKV + buf * ATT_BUF3 + m * ATT_T + r * ATSTR + q * 16, src);
        }
        if (tid < 16)
            CP_ASYNC16(sMk + buf * 256 + tid * 16,
                       mask + (size_t)b * (3 * SS) + kt * 64 + tid * 4);
        CP_COMMIT();
    };
    load_tile(0, 0);

    float o[8][4];
#pragma unroll
    for (int j = 0; j < 8; j++)
#pragma unroll
        for (int r = 0; r < 4; r++) o[j][r] = 0.f;
    float mr0 = -INFINITY, mr1 = -INFINITY, l0 = 0.f, l1 = 0.f;

    for (int kt = 0; kt < 8; kt++) {
        const int buf = kt & 1;
        if (kt < 7) {
            load_tile(kt + 1, buf ^ 1);
            asm volatile("cp.async.wait_group 1;" ::: "memory");
        } else {
            asm volatile("cp.async.wait_group 0;" ::: "memory");
        }
        __syncthreads();

        const uint32_t kB = sKV + buf * ATT_BUF3;
        const int* msk = (const int*)(dsm + (ATT_QB + 2 * ATT_BUF3) + buf * 256);

        // ---- scores: single Qh*Kh ----
        float s[8][4];
#pragma unroll
        for (int j = 0; j < 8; j++)
#pragma unroll
            for (int r = 0; r < 4; r++) s[j][r] = 0.f;
#pragma unroll
        for (int ks = 0; ks < 4; ks++) {
            uint32_t qh[4];
            ldsm4(qh, sQ + (w * 16 + a_r) * ATSTR + ks * 32 + a_ko);
#pragma unroll
            for (int jp = 0; jp < 4; jp++) {
                uint32_t bh4[4];
                ldsm4(bh4, kB + (jp * 16 + b_r) * ATSTR + ks * 32 + b_ko);
                mma_f16(s[2*jp],   qh, bh4[0], bh4[1]);
                mma_f16(s[2*jp+1], qh, bh4[2], bh4[3]);
            }
        }

        // ---- online softmax ----
        float tm0 = -INFINITY, tm1 = -INFINITY;
#pragma unroll
        for (int j = 0; j < 8; j++) {
            const int c0 = 8 * j + 2 * t4;
            const bool v0 = msk[c0] != 0, v1 = msk[c0 + 1] != 0;
            s[j][0] = v0 ? s[j][0] * 0.125f : -INFINITY;
            s[j][1] = v1 ? s[j][1] * 0.125f : -INFINITY;
            s[j][2] = v0 ? s[j][2] * 0.125f : -INFINITY;
            s[j][3] = v1 ? s[j][3] * 0.125f : -INFINITY;
            tm0 = fmaxf(tm0, fmaxf(s[j][0], s[j][1]));
            tm1 = fmaxf(tm1, fmaxf(s[j][2], s[j][3]));
        }
        tm0 = fmaxf(tm0, __shfl_xor_sync(0xffffffffu, tm0, 1));
        tm0 = fmaxf(tm0, __shfl_xor_sync(0xffffffffu, tm0, 2));
        tm1 = fmaxf(tm1, __shfl_xor_sync(0xffffffffu, tm1, 1));
        tm1 = fmaxf(tm1, __shfl_xor_sync(0xffffffffu, tm1, 2));
        const float nm0 = fmaxf(mr0, tm0), nm1 = fmaxf(mr1, tm1);
        const float nb0 = (nm0 == -INFINITY) ? 0.f : nm0;
        const float nb1 = (nm1 == -INFINITY) ? 0.f : nm1;
        const float cr0 = __expf(mr0 - nb0), cr1 = __expf(mr1 - nb1);
        float sum0 = 0.f, sum1 = 0.f;
#pragma unroll
        for (int j = 0; j < 8; j++) {
            s[j][0] = __expf(s[j][0] - nb0);
            s[j][1] = __expf(s[j][1] - nb0);
            s[j][2] = __expf(s[j][2] - nb1);
            s[j][3] = __expf(s[j][3] - nb1);
            sum0 += s[j][0] + s[j][1];
            sum1 += s[j][2] + s[j][3];
            o[j][0] *= cr0; o[j][1] *= cr0;
            o[j][2] *= cr1; o[j][3] *= cr1;
        }
        sum0 += __shfl_xor_sync(0xffffffffu, sum0, 1);
        sum0 += __shfl_xor_sync(0xffffffffu, sum0, 2);
        sum1 += __shfl_xor_sync(0xffffffffu, sum1, 1);
        sum1 += __shfl_xor_sync(0xffffffffu, sum1, 2);
        l0 = l0 * cr0 + sum0;
        l1 = l1 * cr1 + sum1;
        mr0 = nm0; mr1 = nm1;

        // ---- O += P*(Vh+Vl) ----
#pragma unroll
        for (int kt2 = 0; kt2 < 4; kt2++) {
            uint32_t pah[4];
            {
                const float* pj0 = s[2 * kt2];
                const float* pj1 = s[2 * kt2 + 1];
                pah[0] = packh(pj0[0], pj0[1]);
                pah[1] = packh(pj0[2], pj0[3]);
                pah[2] = packh(pj1[0], pj1[1]);
                pah[3] = packh(pj1[2], pj1[3]);
            }
#pragma unroll
            for (int jp = 0; jp < 4; jp++) {
                uint32_t vh4[4], vl4[4];
                const uint32_t va = kB + ATT_T
                    + (kt2 * 16 + a_r) * ATSTR + jp * 32 + a_ko;
                ldsm4t(vh4, va);
                ldsm4t(vl4, va + ATT_T);
                mma_f16(o[2*jp],   pah, vh4[0], vh4[1]);
                mma_f16(o[2*jp],   pah, vl4[0], vl4[1]);
                mma_f16(o[2*jp+1], pah, vh4[2], vh4[3]);
                mma_f16(o[2*jp+1], pah, vl4[2], vl4[3]);
            }
        }
        __syncthreads();
    }

    const float inv0 = (l0 > 0.f) ? (1.f / l0) : 0.f;
    const float inv1 = (l1 > 0.f) ? (1.f / l1) : 0.f;
    const size_t ob0 = (size_t)(b * SS + qblk + w * 16 + gid) * CC + h * 64;
    const size_t ob1 = ob0 + (size_t)8 * CC;
#pragma unroll
    for (int j = 0; j < 8; j++) {
        const int col = 8 * j + 2 * t4;
        const float v0 = o[j][0] * inv0, v1 = o[j][1] * inv0;
        const float v2 = o[j][2] * inv1, v3 = o[j][3] * inv1;
        const __half h0 = __float2half_rn(v0);
        const __half h1 = __float2half_rn(v1);
        const __half h2 = __float2half_rn(v2);
        const __half h3 = __float2half_rn(v3);
        *(__half2*)(xoh + ob0 + col) = __halves2half2(h0, h1);
        *(__half2*)(xoh + ob1 + col) = __halves2half2(h2, h3);
        *(__half2*)(xol + ob0 + col) = __halves2half2(
            __float2half_rn(v0 - __half2float(h0)),
            __float2half_rn(v1 - __half2float(h1)));
        *(__half2*)(xol + ob1 + col) = __halves2half2(
            __float2half_rn(v2 - __half2float(h2)),
            __float2half_rn(v3 - __half2float(h3)));
    }
}

// ---------------- launch -----------------------------------------------------
extern "C" void kernel_launch(void* const* d_in, const int* in_sizes, int n_in,
                              void* d_out, int out_size)
{
    const float* x        = (const float*)d_in[0];
    const int*   mask     = (const int*)d_in[1];
    const float* qkv_w    = (const float*)d_in[2];
    const float* qkv_la   = (const float*)d_in[3];
    const float* qkv_lb   = (const float*)d_in[4];
    const float* proj_w   = (const float*)d_in[5];
    const float* proj_b   = (const float*)d_in[6];
    const float* proj_la  = (const float*)d_in[7];
    const float* proj_lb  = (const float*)d_in[8];
    const float* fc1_w    = (const float*)d_in[9];
    const float* fc1_b    = (const float*)d_in[10];
    const float* fc1_la   = (const float*)d_in[11];
    const float* fc1_lb   = (const float*)d_in[12];
    const float* fc2_w    = (const float*)d_in[13];
    const float* fc2_b    = (const float*)d_in[14];
    const float* fc2_la   = (const float*)d_in[15];
    const float* fc2_lb   = (const float*)d_in[16];
    float* out = (float*)d_out;

    __half *qkvh,*qkvl,*ah,*al,*ah2,*al2,*a2h,*a2l;
    __half *wq,*w1,*w2,*wp,*lq,*l1,*l2,*lp;
    cudaGetSymbolAddress((void**)&qkvh, g_qkvh); cudaGetSymbolAddress((void**)&qkvl, g_qkvl);
    cudaGetSymbolAddress((void**)&ah,  g_ah);   cudaGetSymbolAddress((void**)&al,  g_al);
    cudaGetSymbolAddress((void**)&ah2, g_ah2);  cudaGetSymbolAddress((void**)&al2, g_al2);
    cudaGetSymbolAddress((void**)&a2h, g_a2h);  cudaGetSymbolAddress((void**)&a2l, g_a2l);
    cudaGetSymbolAddress((void**)&wq, g_wqkv);
    cudaGetSymbolAddress((void**)&w1, g_wfc1);
    cudaGetSymbolAddress((void**)&w2, g_wfc2);
    cudaGetSymbolAddress((void**)&wp, g_wproj);
    cudaGetSymbolAddress((void**)&lq, g_lbqkv);
    cudaGetSymbolAddress((void**)&l1, g_lbfc1);
    cudaGetSymbolAddress((void**)&l2, g_lbfc2);
    cudaGetSymbolAddress((void**)&lp, g_lbproj);

    cudaFuncSetAttribute(mm_gemm_kernel,
                         cudaFuncAttributeMaxDynamicSharedMemorySize, DSMB);
    cudaFuncSetAttribute(attn_mma_kernel,
                         cudaFuncAttributeMaxDynamicSharedMemorySize, ATT_SMEM);

    const int M = MTOT;
    const int actN4 = M * CC / 4;

    // ---- weight prep (transpose + fp16 convert) ----
    transpose_convert_kernel<<<dim3(3*CC/32, CC/32), 256>>>(qkv_w, wq, CC, 3*CC);
    transpose_convert_kernel<<<dim3(CC/32,  CC/32), 256>>>(fc1_w, w1, CC, CC);
    transpose_convert_kernel<<<dim3(CC/32,  CC/32), 256>>>(fc2_w, w2, CC, CC);
    transpose_convert_kernel<<<dim3(CC/32,  CC/32), 256>>>(proj_w, wp, CC, CC);
    transpose_convert_kernel<<<dim3(3*CC/32, 1), 256>>>(qkv_lb, lq, RR, 3*CC);
    transpose_convert_kernel<<<dim3(CC/32, 1), 256>>>(fc1_lb, l1, RR, CC);
    transpose_convert_kernel<<<dim3(CC/32, 1), 256>>>(fc2_lb, l2, RR, CC);
    transpose_convert_kernel<<<dim3(CC/32, 1), 256>>>(proj_lb, lp, RR, CC);

    // ---- x -> fp16 hi/lo ----
    convert_hilo_kernel<<<actN4/256, 256>>>(x, ah, al, actN4);

    // ---- qkv: out fp16 hi/lo ----
    gemm_la_h_kernel<<<M/32, 256>>>(ah, qkv_la, a2h, a2l, CC);
    mm_gemm_kernel<<<dim3(3*CC/128, M/128), 256, DSMB>>>(
        ah, al, a2h, a2l, wq, lq, nullptr, qkvh, qkvl,
        nullptr, nullptr, nullptr, 0, 3*CC);

    // ---- attention -> ah/al (xo hi/lo) ----
    attn_mma_kernel<<<dim3(SS/128, BB*HH), 256, ATT_SMEM>>>(
        qkvh, qkvl, mask, ah, al);

    // ---- fc1 (gelu): out ah2/al2 ----
    gemm_la_h_kernel<<<M/32, 256>>>(ah, fc1_la, a2h, a2l, CC);
    mm_gemm_kernel<<<dim3(CC/128, M/128), 256, DSMB>>>(
        ah, al, a2h, a2l, w1, l1, nullptr, ah2, al2, fc1_b,
        nullptr, nullptr, 1, CC);

    // ---- fc2 (+ residual ah/al): out qkvh/qkvl (xo2 hi/lo) ----
    gemm_la_h_kernel<<<M/32, 256>>>(ah2, fc2_la, a2h, a2l, CC);
    mm_gemm_kernel<<<dim3(CC/128, M/128), 256, DSMB>>>(
        ah2, al2, a2h, a2l, w2, l2, nullptr, qkvh, qkvl, fc2_b,
        ah, al, 0, CC);

    // ---- proj -> out (fp32) ----
    gemm_la_h_kernel<<<M/32, 256>>>(qkvh, proj_la, a2h, a2l, CC);
    mm_gemm_kernel<<<dim3(CC/128, M/128), 256, DSMB>>>(
        qkvh, qkvl, a2h, a2l, wp, lp, out, nullptr, nullptr, proj_b,
        nullptr, nullptr, 0, CC);
}

// round 17
// speedup vs baseline: 4.8126x; 1.3456x over previous
#include <cuda_runtime.h>
#include <cuda_fp16.h>
#include <math.h>
#include <stdint.h>

#define BB 8
#define SS 512
#define CC 1024
#define HH 16
#define RR 32
#define MTOT (BB*SS)          // 4096
#define KK CC                 // GEMM K = 1024

// ---------------- fp16 scratch ----------------------------------------------
__device__ __half g_qkvh[MTOT * 3 * CC], g_qkvl[MTOT * 3 * CC];
__device__ __half g_ah [MTOT * CC], g_al [MTOT * CC];   // act pair A
__device__ __half g_ah2[MTOT * CC], g_al2[MTOT * CC];   // act pair B
__device__ __half g_a2h[MTOT * RR];
__device__ __half g_wqkv[3*CC*CC];                      // weights fp16 [N,K]
__device__ __half g_wfc1[CC*CC];
__device__ __half g_wfc2[CC*CC];
__device__ __half g_wproj[CC*CC];
__device__ __half g_lbqkv[3*CC*RR];                     // [N,32]
__device__ __half g_lbfc1[CC*RR];
__device__ __half g_lbfc2[CC*RR];
__device__ __half g_lbproj[CC*RR];

// ---------------- helpers ----------------------------------------------------
__device__ __forceinline__ float gelu_exact(float x) {
    return 0.5f * x * (1.0f + erff(x * 0.70710678118654752440f));
}
__device__ __forceinline__ void mma_f16(float* c, const uint32_t* a,
                                        uint32_t b0, uint32_t b1) {
    asm volatile(
        "mma.sync.aligned.m16n8k16.row.col.f32.f16.f16.f32 "
        "{%0,%1,%2,%3}, {%4,%5,%6,%7}, {%8,%9}, {%0,%1,%2,%3};"
        : "+f"(c[0]), "+f"(c[1]), "+f"(c[2]), "+f"(c[3])
        : "r"(a[0]), "r"(a[1]), "r"(a[2]), "r"(a[3]), "r"(b0), "r"(b1));
}
__device__ __forceinline__ void ldsm4(uint32_t* r, uint32_t addr) {
    asm volatile("ldmatrix.sync.aligned.m8n8.x4.shared.b16 {%0,%1,%2,%3}, [%4];"
        : "=r"(r[0]), "=r"(r[1]), "=r"(r[2]), "=r"(r[3]) : "r"(addr));
}
__device__ __forceinline__ void ldsm4t(uint32_t* r, uint32_t addr) {
    asm volatile("ldmatrix.sync.aligned.m8n8.x4.trans.shared.b16 {%0,%1,%2,%3}, [%4];"
        : "=r"(r[0]), "=r"(r[1]), "=r"(r[2]), "=r"(r[3]) : "r"(addr));
}
#define CP_ASYNC16(dst_u32, src_ptr) \
    asm volatile("cp.async.cg.shared.global [%0], [%1], 16;" \
                 :: "r"(dst_u32), "l"(src_ptr))
#define CP_COMMIT() asm volatile("cp.async.commit_group;" ::: "memory")

__device__ __forceinline__ uint32_t packh(float x, float y) {
    __half2 t = __floats2half2_rn(x, y);
    return *(uint32_t*)&t;
}

// ---------------- HMMA fp16 GEMM (A-hi single, 4-stage pipeline) -------------
// C/Ch[M,N] = Ah[M,K] @ B[N,K]^T + A2h[M,32] @ LB[N,32]^T
//             (+bias) (gelu?) (+res from fp16 hi/lo pair)
#define TCSTRIDE 80            // bytes per smem row (32 fp16 + pad)
#define MATB 10240             // bytes per matrix tile (128 rows)
#define STAGEB (2*MATB)        // 20480: Ah, B
#define NSTAGE 4
#define DSMB (NSTAGE*STAGEB)   // 81920

__global__ __launch_bounds__(256, 2) void mm_gemm_kernel(
    const __half* __restrict__ Ah,  const __half* __restrict__ A2h,
    const __half* __restrict__ B,   const __half* __restrict__ LB,
    float* __restrict__ C, __half* __restrict__ Ch,
    __half* __restrict__ Cl, const float* __restrict__ bias,
    const __half* __restrict__ resh, const __half* __restrict__ resl,
    int act, int N)
{
    extern __shared__ char dsm[];
    const int tid = threadIdx.x;
    const int row0 = blockIdx.y * 128;
    const int col0 = blockIdx.x * 128;
    const int w = tid >> 5, lane = tid & 31;
    const int gid = lane >> 2, t4 = lane & 3;
    const int wm = (w & 3) * 32, wn = (w >> 2) * 64;

    const uint32_t smem0 = (uint32_t)__cvta_generic_to_shared(dsm);

    const int a_r  = (lane & 15);
    const int a_ko = (lane >> 4) * 16;
    const int b_r  = (lane & 7) + ((lane >> 4) << 3);
    const int b_ko = ((lane >> 3) & 1) * 16;

    float acc[2][8][4];
#pragma unroll
    for (int i = 0; i < 2; i++)
#pragma unroll
        for (int j = 0; j < 8; j++)
#pragma unroll
            for (int r = 0; r < 4; r++) acc[i][j][r] = 0.f;

    auto load_stage = [&](int buf, int kc) {
        const uint32_t sb = smem0 + buf * STAGEB;
        const bool lora = (kc == 32);
        const int koff = lora ? 0 : kc * 32;
        const int strd = lora ? RR : KK;
        const __half* p0 = lora ? A2h : Ah;
        const __half* p1 = lora ? LB : B;
#pragma unroll
        for (int t = 0; t < 4; t++) {
            const int idx = tid + t * 256;       // 0..1023
            const int m = idx >> 9;              // 0=A 1=B
            const int r = (idx >> 2) & 127;
            const int q = idx & 3;
            const __half* base = m ? p1 : p0;
            const int grow = (m ? col0 : row0) + r;
            const __half* src = base + (size_t)grow * strd + koff + q * 8;
            const uint32_t dst = sb + m * MATB + r * TCSTRIDE + q * 16;
            CP_ASYNC16(dst, src);
        }
        CP_COMMIT();
    };

    auto compute = [&](int buf) {
        const uint32_t sb = smem0 + buf * STAGEB;
#pragma unroll
        for (int ks = 0; ks < 2; ks++) {
            const int kb = ks * 32;              // bytes
            uint32_t a[2][4];
#pragma unroll
            for (int i = 0; i < 2; i++)
                ldsm4(a[i], sb + (wm + i * 16 + a_r) * TCSTRIDE + kb + a_ko);
#pragma unroll
            for (int jp = 0; jp < 4; jp++) {
                uint32_t bb[4];
                ldsm4(bb, sb + MATB + (wn + jp * 16 + b_r) * TCSTRIDE + kb + b_ko);
#pragma unroll
                for (int i = 0; i < 2; i++) {
                    mma_f16(acc[i][2*jp],   a[i], bb[0], bb[1]);
                    mma_f16(acc[i][2*jp+1], a[i], bb[2], bb[3]);
                }
            }
        }
    };

    // 4-stage pipeline, one barrier per chunk
    load_stage(0, 0);
    load_stage(1, 1);
    load_stage(2, 2);
    for (int kc = 0; kc < 33; kc++) {
        if (kc < 31) {
            asm volatile("cp.async.wait_group 2;" ::: "memory");
        } else if (kc == 31) {
            asm volatile("cp.async.wait_group 1;" ::: "memory");
        } else {
            asm volatile("cp.async.wait_group 0;" ::: "memory");
        }
        __syncthreads();
        if (kc + 3 < 33) load_stage((kc + 3) & 3, kc + 3);
        compute(kc & 3);
    }

#pragma unroll
    for (int i = 0; i < 2; i++) {
        const int r0 = row0 + wm + i * 16 + gid;
#pragma unroll
        for (int j = 0; j < 8; j++) {
            const int col = col0 + wn + j * 8 + t4 * 2;
            float v0 = acc[i][j][0], v1 = acc[i][j][1];
            float v2 = acc[i][j][2], v3 = acc[i][j][3];
            if (bias) {
                const float b0 = bias[col], b1 = bias[col + 1];
                v0 += b0; v1 += b1; v2 += b0; v3 += b1;
            }
            if (act) {
                v0 = gelu_exact(v0); v1 = gelu_exact(v1);
                v2 = gelu_exact(v2); v3 = gelu_exact(v3);
            }
            if (resh) {
                const __half2 rh0 = *(const __half2*)(resh + (size_t)r0 * N + col);
                const __half2 rl0 = *(const __half2*)(resl + (size_t)r0 * N + col);
                const __half2 rh1 = *(const __half2*)(resh + (size_t)(r0 + 8) * N + col);
                const __half2 rl1 = *(const __half2*)(resl + (size_t)(r0 + 8) * N + col);
                v0 += __half2float(rh0.x) + __half2float(rl0.x);
                v1 += __half2float(rh0.y) + __half2float(rl0.y);
                v2 += __half2float(rh1.x) + __half2float(rl1.x);
                v3 += __half2float(rh1.y) + __half2float(rl1.y);
            }
            if (C) {
                *(float2*)(C + (size_t)r0 * N + col) = make_float2(v0, v1);
                *(float2*)(C + (size_t)(r0 + 8) * N + col) = make_float2(v2, v3);
            }
            if (Ch) {
                const __half h0 = __float2half_rn(v0);
                const __half h1 = __float2half_rn(v1);
                const __half h2 = __float2half_rn(v2);
                const __half h3 = __float2half_rn(v3);
                *(__half2*)(Ch + (size_t)r0 * N + col) = __halves2half2(h0, h1);
                *(__half2*)(Ch + (size_t)(r0 + 8) * N + col) = __halves2half2(h2, h3);
                *(__half2*)(Cl + (size_t)r0 * N + col) = __halves2half2(
                    __float2half_rn(v0 - __half2float(h0)),
                    __float2half_rn(v1 - __half2float(h1)));
                *(__half2*)(Cl + (size_t)(r0 + 8) * N + col) = __halves2half2(
                    __float2half_rn(v2 - __half2float(h2)),
                    __float2half_rn(v3 - __half2float(h3)));
            }
        }
    }
}

// ---------------- prep kernels ----------------------------------------------
__global__ __launch_bounds__(256) void transpose_convert_kernel(
    const float* __restrict__ W, __half* __restrict__ Th, int K, int N)
{
    __shared__ float s[32][33];
    const int tx = threadIdx.x & 31, ty = threadIdx.x >> 5;
    const int n0 = blockIdx.x * 32, k0 = blockIdx.y * 32;
#pragma unroll
    for (int i = 0; i < 4; i++)
        s[ty + 8*i][tx] = W[(size_t)(k0 + ty + 8*i) * N + n0 + tx];
    __syncthreads();
#pragma unroll
    for (int i = 0; i < 4; i++) {
        const int n = ty + 8*i;
        Th[(size_t)(n0 + n) * K + k0 + tx] = __float2half_rn(s[tx][n]);
    }
}

__global__ __launch_bounds__(256) void convert_hilo_kernel(
    const float* __restrict__ in, __half* __restrict__ oh,
    __half* __restrict__ ol, int n4)
{
    const int i = blockIdx.x * 256 + threadIdx.x;
    if (i >= n4) return;
    const float4 v = ((const float4*)in)[i];
    const __half hx = __float2half_rn(v.x);
    const __half hy = __float2half_rn(v.y);
    const __half hz = __float2half_rn(v.z);
    const __half hw = __float2half_rn(v.w);
    ((__half2*)oh)[2*i]   = __halves2half2(hx, hy);
    ((__half2*)oh)[2*i+1] = __halves2half2(hz, hw);
    ((__half2*)ol)[2*i]   = __halves2half2(
        __float2half_rn(v.x - __half2float(hx)),
        __float2half_rn(v.y - __half2float(hy)));
    ((__half2*)ol)[2*i+1] = __halves2half2(
        __float2half_rn(v.z - __half2float(hz)),
        __float2half_rn(v.w - __half2float(hw)));
}

// ---------------- LoRA A-projection (fp16 A-hi in, fp16 hi out) -------------
__global__ __launch_bounds__(256) void gemm_la_h_kernel(
    const __half* __restrict__ A, const float* __restrict__ LA,
    __half* __restrict__ A2h, int K)
{
    __shared__ float sA[32 * 32];
    __shared__ float sLAt[32 * 36];
    const int tid = threadIdx.x;
    const int row0 = blockIdx.x * 32;
    const int col = tid & 31;
    const int rgrp = tid >> 5;

    float s[4] = {0.f, 0.f, 0.f, 0.f};

    for (int k0 = 0; k0 < K; k0 += 32) {
        __syncthreads();
        {
            const int r = tid >> 3, c = (tid & 7) * 4;
            const uint2 v = *(const uint2*)(A + (size_t)(row0 + r) * K + k0 + c);
            const __half2 h01 = *(const __half2*)&v.x;
            const __half2 h23 = *(const __half2*)&v.y;
            sA[r * 32 + c + 0] = __half2float(h01.x);
            sA[r * 32 + c + 1] = __half2float(h01.y);
            sA[r * 32 + c + 2] = __half2float(h23.x);
            sA[r * 32 + c + 3] = __half2float(h23.y);
        }
#pragma unroll
        for (int t = 0; t < 4; t++) {
            const int idx = tid + t * 256;
            const int kk = idx >> 5, c = idx & 31;
            sLAt[c * 36 + kk] = LA[(size_t)(k0 + kk) * 32 + c];
        }
        __syncthreads();
#pragma unroll
        for (int kk = 0; kk < 32; kk += 4) {
            const float4 la = *(const float4*)&sLAt[col * 36 + kk];
#pragma unroll
            for (int rr = 0; rr < 4; rr++) {
                const float4 a = *(const float4*)&sA[(rgrp + rr * 8) * 32 + kk];
                s[rr] += a.x * la.x + a.y * la.y + a.z * la.z + a.w * la.w;
            }
        }
    }
#pragma unroll
    for (int rr = 0; rr < 4; rr++)
        A2h[(size_t)(row0 + rgrp + rr * 8) * 32 + col] = __float2half_rn(s[rr]);
}

// ---------------- tensor-core flash attention --------------------------------
// QK: Qh*Kh (1 MMA); PV: Ph*(Vh+Vl) (2 MMAs). Output fp16 hi/lo.
#define ATSTR 144              // smem row stride bytes
#define ATT_QB (128*ATSTR)     // 18432 (Qh only)
#define ATT_T  (64*ATSTR)      // 9216
#define ATT_BUF3 (3*ATT_T)     // Kh, Vh, Vl = 27648
#define ATT_SMEM (ATT_QB + 2*ATT_BUF3 + 512)

__global__ __launch_bounds__(256, 1) void attn_mma_kernel(
    const __half* __restrict__ qkvh,
    const __half* __restrict__ qkvl,
    const int* __restrict__ mask,
    __half* __restrict__ xoh, __half* __restrict__ xol)
{
    extern __shared__ char dsm[];
    const int tid = threadIdx.x;
    const int w = tid >> 5, lane = tid & 31;
    const int gid = lane >> 2, t4 = lane & 3;
    const int bh = blockIdx.y, b = bh >> 4, h = bh & 15;
    const int qblk = blockIdx.x * 128;

    const uint32_t s0 = (uint32_t)__cvta_generic_to_shared(dsm);
    const uint32_t sQ = s0;
    const uint32_t sKV = s0 + ATT_QB;
    const uint32_t sMk = sKV + 2 * ATT_BUF3;

    const int a_r = lane & 15, a_ko = (lane >> 4) * 16;
    const int b_r = (lane & 7) + ((lane >> 4) << 3);
    const int b_ko = ((lane >> 3) & 1) * 16;

#pragma unroll
    for (int t = 0; t < 4; t++) {
        const int idx = tid + t * 256;           // 0..1023
        const int r = idx >> 3;
        const int q = idx & 7;
        const __half* src = qkvh
            + (size_t)(b * SS + qblk + r) * 3072 + h * 64 + q * 8;
        CP_ASYNC16(sQ + r * ATSTR + q * 16, src);
    }
    auto load_tile = [&](int kt, int buf) {
#pragma unroll
        for (int t = 0; t < 6; t++) {
            const int idx = tid + t * 256;       // 0..1535
            const int m = idx >> 9;              // 0=Kh 1=Vh 2=Vl
            const int r = (idx >> 3) & 63;
            const int q = idx & 7;
            const int colb = ((m == 0) ? 1024 : 2048) + h * 64;
            const __half* src = ((m == 2) ? qkvl : qkvh)
                + (size_t)(b * SS + kt * 64 + r) * 3072 + colb + q * 8;
            CP_ASYNC16(sKV + buf * ATT_BUF3 + m * ATT_T + r * ATSTR + q * 16, src);
        }
        if (tid < 16)
            CP_ASYNC16(sMk + buf * 256 + tid * 16,
                       mask + (size_t)b * (3 * SS) + kt * 64 + tid * 4);
        CP_COMMIT();
    };
    load_tile(0, 0);

    float o[8][4];
#pragma unroll
    for (int j = 0; j < 8; j++)
#pragma unroll
        for (int r = 0; r < 4; r++) o[j][r] = 0.f;
    float mr0 = -INFINITY, mr1 = -INFINITY, l0 = 0.f, l1 = 0.f;

    for (int kt = 0; kt < 8; kt++) {
        const int buf = kt & 1;
        if (kt < 7) {
            load_tile(kt + 1, buf ^ 1);
            asm volatile("cp.async.wait_group 1;" ::: "memory");
        } else {
            asm volatile("cp.async.wait_group 0;" ::: "memory");
        }
        __syncthreads();

        const uint32_t kB = sKV + buf * ATT_BUF3;
        const int* msk = (const int*)(dsm + (ATT_QB + 2 * ATT_BUF3) + buf * 256);

        float s[8][4];
#pragma unroll
        for (int j = 0; j < 8; j++)
#pragma unroll
            for (int r = 0; r < 4; r++) s[j][r] = 0.f;
#pragma unroll
        for (int ks = 0; ks < 4; ks++) {
            uint32_t qh[4];
            ldsm4(qh, sQ + (w * 16 + a_r) * ATSTR + ks * 32 + a_ko);
#pragma unroll
            for (int jp = 0; jp < 4; jp++) {
                uint32_t bh4[4];
                ldsm4(bh4, kB + (jp * 16 + b_r) * ATSTR + ks * 32 + b_ko);
                mma_f16(s[2*jp],   qh, bh4[0], bh4[1]);
                mma_f16(s[2*jp+1], qh, bh4[2], bh4[3]);
            }
        }

        float tm0 = -INFINITY, tm1 = -INFINITY;
#pragma unroll
        for (int j = 0; j < 8; j++) {
            const int c0 = 8 * j + 2 * t4;
            const bool v0 = msk[c0] != 0, v1 = msk[c0 + 1] != 0;
            s[j][0] = v0 ? s[j][0] * 0.125f : -INFINITY;
            s[j][1] = v1 ? s[j][1] * 0.125f : -INFINITY;
            s[j][2] = v0 ? s[j][2] * 0.125f : -INFINITY;
            s[j][3] = v1 ? s[j][3] * 0.125f : -INFINITY;
            tm0 = fmaxf(tm0, fmaxf(s[j][0], s[j][1]));
            tm1 = fmaxf(tm1, fmaxf(s[j][2], s[j][3]));
        }
        tm0 = fmaxf(tm0, __shfl_xor_sync(0xffffffffu, tm0, 1));
        tm0 = fmaxf(tm0, __shfl_xor_sync(0xffffffffu, tm0, 2));
        tm1 = fmaxf(tm1, __shfl_xor_sync(0xffffffffu, tm1, 1));
        tm1 = fmaxf(tm1, __shfl_xor_sync(0xffffffffu, tm1, 2));
        const float nm0 = fmaxf(mr0, tm0), nm1 = fmaxf(mr1, tm1);
        const float nb0 = (nm0 == -INFINITY) ? 0.f : nm0;
        const float nb1 = (nm1 == -INFINITY) ? 0.f : nm1;
        const float cr0 = __expf(mr0 - nb0), cr1 = __expf(mr1 - nb1);
        float sum0 = 0.f, sum1 = 0.f;
#pragma unroll
        for (int j = 0; j < 8; j++) {
            s[j][0] = __expf(s[j][0] - nb0);
            s[j][1] = __expf(s[j][1] - nb0);
            s[j][2] = __expf(s[j][2] - nb1);
            s[j][3] = __expf(s[j][3] - nb1);
            sum0 += s[j][0] + s[j][1];
            sum1 += s[j][2] + s[j][3];
            o[j][0] *= cr0; o[j][1] *= cr0;
            o[j][2] *= cr1; o[j][3] *= cr1;
        }
        sum0 += __shfl_xor_sync(0xffffffffu, sum0, 1);
        sum0 += __shfl_xor_sync(0xffffffffu, sum0, 2);
        sum1 += __shfl_xor_sync(0xffffffffu, sum1, 1);
        sum1 += __shfl_xor_sync(0xffffffffu, sum1, 2);
        l0 = l0 * cr0 + sum0;
        l1 = l1 * cr1 + sum1;
        mr0 = nm0; mr1 = nm1;

#pragma unroll
        for (int kt2 = 0; kt2 < 4; kt2++) {
            uint32_t pah[4];
            {
                const float* pj0 = s[2 * kt2];
                const float* pj1 = s[2 * kt2 + 1];
                pah[0] = packh(pj0[0], pj0[1]);
                pah[1] = packh(pj0[2], pj0[3]);
                pah[2] = packh(pj1[0], pj1[1]);
                pah[3] = packh(pj1[2], pj1[3]);
            }
#pragma unroll
            for (int jp = 0; jp < 4; jp++) {
                uint32_t vh4[4], vl4[4];
                const uint32_t va = kB + ATT_T
                    + (kt2 * 16 + a_r) * ATSTR + jp * 32 + a_ko;
                ldsm4t(vh4, va);
                ldsm4t(vl4, va + ATT_T);
                mma_f16(o[2*jp],   pah, vh4[0], vh4[1]);
                mma_f16(o[2*jp],   pah, vl4[0], vl4[1]);
                mma_f16(o[2*jp+1], pah, vh4[2], vh4[3]);
                mma_f16(o[2*jp+1], pah, vl4[2], vl4[3]);
            }
        }
        __syncthreads();
    }

    const float inv0 = (l0 > 0.f) ? (1.f / l0) : 0.f;
    const float inv1 = (l1 > 0.f) ? (1.f / l1) : 0.f;
    const size_t ob0 = (size_t)(b * SS + qblk + w * 16 + gid) * CC + h * 64;
    const size_t ob1 = ob0 + (size_t)8 * CC;
#pragma unroll
    for (int j = 0; j < 8; j++) {
        const int col = 8 * j + 2 * t4;
        const float v0 = o[j][0] * inv0, v1 = o[j][1] * inv0;
        const float v2 = o[j][2] * inv1, v3 = o[j][3] * inv1;
        const __half h0 = __float2half_rn(v0);
        const __half h1 = __float2half_rn(v1);
        const __half h2 = __float2half_rn(v2);
        const __half h3 = __float2half_rn(v3);
        *(__half2*)(xoh + ob0 + col) = __halves2half2(h0, h1);
        *(__half2*)(xoh + ob1 + col) = __halves2half2(h2, h3);
        *(__half2*)(xol + ob0 + col) = __halves2half2(
            __float2half_rn(v0 - __half2float(h0)),
            __float2half_rn(v1 - __half2float(h1)));
        *(__half2*)(xol + ob1 + col) = __halves2half2(
            __float2half_rn(v2 - __half2float(h2)),
            __float2half_rn(v3 - __half2float(h3)));
    }
}

// ---------------- launch -----------------------------------------------------
extern "C" void kernel_launch(void* const* d_in, const int* in_sizes, int n_in,
                              void* d_out, int out_size)
{
    const float* x        = (const float*)d_in[0];
    const int*   mask     = (const int*)d_in[1];
    const float* qkv_w    = (const float*)d_in[2];
    const float* qkv_la   = (const float*)d_in[3];
    const float* qkv_lb   = (const float*)d_in[4];
    const float* proj_w   = (const float*)d_in[5];
    const float* proj_b   = (const float*)d_in[6];
    const float* proj_la  = (const float*)d_in[7];
    const float* proj_lb  = (const float*)d_in[8];
    const float* fc1_w    = (const float*)d_in[9];
    const float* fc1_b    = (const float*)d_in[10];
    const float* fc1_la   = (const float*)d_in[11];
    const float* fc1_lb   = (const float*)d_in[12];
    const float* fc2_w    = (const float*)d_in[13];
    const float* fc2_b    = (const float*)d_in[14];
    const float* fc2_la   = (const float*)d_in[15];
    const float* fc2_lb   = (const float*)d_in[16];
    float* out = (float*)d_out;

    __half *qkvh,*qkvl,*ah,*al,*ah2,*al2,*a2h;
    __half *wq,*w1,*w2,*wp,*lq,*l1,*l2,*lp;
    cudaGetSymbolAddress((void**)&qkvh, g_qkvh); cudaGetSymbolAddress((void**)&qkvl, g_qkvl);
    cudaGetSymbolAddress((void**)&ah,  g_ah);   cudaGetSymbolAddress((void**)&al,  g_al);
    cudaGetSymbolAddress((void**)&ah2, g_ah2);  cudaGetSymbolAddress((void**)&al2, g_al2);
    cudaGetSymbolAddress((void**)&a2h, g_a2h);
    cudaGetSymbolAddress((void**)&wq, g_wqkv);
    cudaGetSymbolAddress((void**)&w1, g_wfc1);
    cudaGetSymbolAddress((void**)&w2, g_wfc2);
    cudaGetSymbolAddress((void**)&wp, g_wproj);
    cudaGetSymbolAddress((void**)&lq, g_lbqkv);
    cudaGetSymbolAddress((void**)&l1, g_lbfc1);
    cudaGetSymbolAddress((void**)&l2, g_lbfc2);
    cudaGetSymbolAddress((void**)&lp, g_lbproj);

    cudaFuncSetAttribute(mm_gemm_kernel,
                         cudaFuncAttributeMaxDynamicSharedMemorySize, DSMB);
    cudaFuncSetAttribute(attn_mma_kernel,
                         cudaFuncAttributeMaxDynamicSharedMemorySize, ATT_SMEM);

    const int M = MTOT;
    const int actN4 = M * CC / 4;

    // ---- weight prep (transpose + fp16 convert) ----
    transpose_convert_kernel<<<dim3(3*CC/32, CC/32), 256>>>(qkv_w, wq, CC, 3*CC);
    transpose_convert_kernel<<<dim3(CC/32,  CC/32), 256>>>(fc1_w, w1, CC, CC);
    transpose_convert_kernel<<<dim3(CC/32,  CC/32), 256>>>(fc2_w, w2, CC, CC);
    transpose_convert_kernel<<<dim3(CC/32,  CC/32), 256>>>(proj_w, wp, CC, CC);
    transpose_convert_kernel<<<dim3(3*CC/32, 1), 256>>>(qkv_lb, lq, RR, 3*CC);
    transpose_convert_kernel<<<dim3(CC/32, 1), 256>>>(fc1_lb, l1, RR, CC);
    transpose_convert_kernel<<<dim3(CC/32, 1), 256>>>(fc2_lb, l2, RR, CC);
    transpose_convert_kernel<<<dim3(CC/32, 1), 256>>>(proj_lb, lp, RR, CC);

    // ---- x -> fp16 hi/lo (hi feeds GEMM; lo unused but harmless) ----
    convert_hilo_kernel<<<actN4/256, 256>>>(x, ah, al, actN4);

    // ---- qkv: out fp16 hi/lo ----
    gemm_la_h_kernel<<<M/32, 256>>>(ah, qkv_la, a2h, CC);
    mm_gemm_kernel<<<dim3(3*CC/128, M/128), 256, DSMB>>>(
        ah, a2h, wq, lq, nullptr, qkvh, qkvl,
        nullptr, nullptr, nullptr, 0, 3*CC);

    // ---- attention -> ah/al (xo hi/lo) ----
    attn_mma_kernel<<<dim3(SS/128, BB*HH), 256, ATT_SMEM>>>(
        qkvh, qkvl, mask, ah, al);

    // ---- fc1 (gelu): out ah2/al2 ----
    gemm_la_h_kernel<<<M/32, 256>>>(ah, fc1_la, a2h, CC);
    mm_gemm_kernel<<<dim3(CC/128, M/128), 256, DSMB>>>(
        ah, a2h, w1, l1, nullptr, ah2, al2, fc1_b,
        nullptr, nullptr, 1, CC);

    // ---- fc2 (+ residual ah/al = xo hi/lo): out qkvh/qkvl (xo2 hi/lo) ----
    gemm_la_h_kernel<<<M/32, 256>>>(ah2, fc2_la, a2h, CC);
    mm_gemm_kernel<<<dim3(CC/128, M/128), 256, DSMB>>>(
        ah2, a2h, w2, l2, nullptr, qkvh, qkvl, fc2_b,
        ah, al, 0, CC);

    // ---- proj -> out (fp32) ----
    gemm_la_h_kernel<<<M/32, 256>>>(qkvh, proj_la, a2h, CC);
    mm_gemm_kernel<<<dim3(CC/128, M/128), 256, DSMB>>>(
        qkvh, a2h, wp, lp, out, nullptr, nullptr, proj_b,
        nullptr, nullptr, 0, CC);
}